// round 1
// baseline (speedup 1.0000x reference)
#include <cuda_runtime.h>
#include <math.h>

#define NMAX 10240
#define D 256
#define TEMP_INV 2.0f
#define LAM 1e-3f
#define BN_EPS 1e-5f

// ------------------------------ scratch ------------------------------
__device__ float g_bufA[NMAX * D];   // xw1 -> xw2 -> trans
__device__ float g_bufB[NMAX * D];   // agg1/h1 -> p
__device__ float g_t[NMAX * D];      // t (BN path)
__device__ float g_h[NMAX * D];      // GCN output h
__device__ float g_z[NMAX * D];
__device__ float g_q[NMAX * D];
__device__ float g_degout[NMAX];
__device__ float g_degin[NMAX];
__device__ float g_musum[D];
__device__ float g_varsum[D];
__device__ float g_s1[NMAX];
__device__ float g_s2[NMAX];
__device__ float g_pos[NMAX];
__device__ float g_neg[NMAX];

// ------------------------------ kernels ------------------------------
__global__ void zero_k(float* p, int n) {
    int i = blockIdx.x * blockDim.x + threadIdx.x;
    if (i < n) p[i] = 0.f;
}

__global__ void degree_k(const int* __restrict__ src, const int* __restrict__ dst,
                         float* dout, float* din, int e) {
    int i = blockIdx.x * blockDim.x + threadIdx.x;
    if (i < e) {
        atomicAdd(&dout[src[i]], 1.f);
        atomicAdd(&din[dst[i]], 1.f);
    }
}

// C[M,Nc] = A[M,K] @ W[K,Nc] (+ bias) (+relu). 64x64 tiles, BK=16, 4x4 micro.
__global__ __launch_bounds__(256) void sgemm_k(
    const float* __restrict__ A, const float* __restrict__ W,
    const float* __restrict__ bias, float* __restrict__ C,
    int M, int K, int Nc, int relu) {
    __shared__ float As[16][64];
    __shared__ float Ws[16][64];
    int tid = threadIdx.x;
    int tx = tid & 15, ty = tid >> 4;
    int m0 = blockIdx.x * 64, n0 = blockIdx.y * 64;
    float acc[4][4] = {};
    for (int k0 = 0; k0 < K; k0 += 16) {
        {
            int row = tid >> 2, kk = (tid & 3) * 4;
            float4 v = make_float4(0.f, 0.f, 0.f, 0.f);
            if (m0 + row < M)
                v = *(const float4*)&A[(size_t)(m0 + row) * K + k0 + kk];
            As[kk + 0][row] = v.x; As[kk + 1][row] = v.y;
            As[kk + 2][row] = v.z; As[kk + 3][row] = v.w;
            int kr = tid >> 4, c = (tid & 15) * 4;
            *(float4*)&Ws[kr][c] = *(const float4*)&W[(size_t)(k0 + kr) * Nc + n0 + c];
        }
        __syncthreads();
#pragma unroll
        for (int kk = 0; kk < 16; kk++) {
            float a[4], b[4];
            *(float4*)a = *(float4*)&As[kk][ty * 4];
            *(float4*)b = *(float4*)&Ws[kk][tx * 4];
#pragma unroll
            for (int ri = 0; ri < 4; ri++)
#pragma unroll
                for (int rj = 0; rj < 4; rj++) acc[ri][rj] += a[ri] * b[rj];
        }
        __syncthreads();
    }
#pragma unroll
    for (int ri = 0; ri < 4; ri++) {
        int r = m0 + ty * 4 + ri;
        if (r < M) {
#pragma unroll
            for (int rj = 0; rj < 4; rj++) {
                int c = n0 + tx * 4 + rj;
                float v = acc[ri][rj] + (bias ? bias[c] : 0.f);
                if (relu) v = fmaxf(v, 0.f);
                C[(size_t)r * Nc + c] = v;
            }
        }
    }
}

// per-edge: agg[dst] += xw[src] * norm_e  (one warp per edge, 256 feats)
__global__ void scatter_k(const float* __restrict__ xw, const int* __restrict__ src,
                          const int* __restrict__ dst, const float* __restrict__ dout,
                          const float* __restrict__ din, float* __restrict__ agg, int e) {
    int warp = (blockIdx.x * blockDim.x + threadIdx.x) >> 5;
    int lane = threadIdx.x & 31;
    if (warp >= e) return;
    int s = src[warp], d = dst[warp];
    float nm = (1.f / sqrtf(dout[s])) * (1.f / sqrtf(din[d]));
    const float* xs = xw + (size_t)s * D;
    float* ad = agg + (size_t)d * D;
#pragma unroll
    for (int c = 0; c < D / 32; c++) {
        int f = lane + 32 * c;
        atomicAdd(&ad[f], xs[f] * nm);
    }
}

__global__ void biasact_k(float* x, const float* __restrict__ b, int M, int relu) {
    int i = blockIdx.x * blockDim.x + threadIdx.x;
    if (i < M * D) {
        float v = x[i] + b[i & (D - 1)];
        if (relu) v = fmaxf(v, 0.f);
        x[i] = v;
    }
}

__global__ void bnstat_k(const float* __restrict__ t, float* musum, float* varsum, int M) {
    int col = threadIdx.x;
    int rpb = (M + gridDim.x - 1) / gridDim.x;
    int r0 = blockIdx.x * rpb;
    int r1 = min(r0 + rpb, M);
    float s = 0.f, s2 = 0.f;
    for (int r = r0; r < r1; r++) {
        float v = t[(size_t)r * D + col];
        s += v; s2 += v * v;
    }
    atomicAdd(&musum[col], s);
    atomicAdd(&varsum[col], s2);
}

__global__ void bnapply_k(float* t, const float* __restrict__ musum,
                          const float* __restrict__ varsum,
                          const float* __restrict__ gamma, const float* __restrict__ beta,
                          int M) {
    int i = blockIdx.x * blockDim.x + threadIdx.x;
    if (i < M * D) {
        int c = i & (D - 1);
        float mu = musum[c] / M;
        float var = varsum[c] / M - mu * mu;
        float v = (t[i] - mu) * (1.f / sqrtf(var + BN_EPS)) * gamma[c] + beta[c];
        t[i] = fmaxf(v, 0.f);  // relu fused
    }
}

// row-wise L2 normalize, one warp per row
__global__ void norml_k(const float* __restrict__ x, float* __restrict__ z, int M) {
    int row = (blockIdx.x * blockDim.x + threadIdx.x) >> 5;
    int lane = threadIdx.x & 31;
    if (row >= M) return;
    const float* xr = x + (size_t)row * D;
    float s = 0.f;
#pragma unroll
    for (int c = 0; c < D / 32; c++) {
        float v = xr[lane + 32 * c];
        s += v * v;
    }
#pragma unroll
    for (int o = 16; o > 0; o >>= 1) s += __shfl_xor_sync(0xffffffffu, s, o);
    float inv = 1.f / fmaxf(sqrtf(s), 1e-12f);
    float* zr = z + (size_t)row * D;
#pragma unroll
    for (int c = 0; c < D / 32; c++) {
        int f = lane + 32 * c;
        zr[f] = xr[f] * inv;
    }
}

// pos: per-edge dot(z[src], q[dst])/TEMP -> atomicAdd pos[dst]
__global__ void pos_k(const float* __restrict__ z, const float* __restrict__ q,
                      const int* __restrict__ src, const int* __restrict__ dst,
                      float* pos, int e) {
    int warp = (blockIdx.x * blockDim.x + threadIdx.x) >> 5;
    int lane = threadIdx.x & 31;
    if (warp >= e) return;
    int s = src[warp], d = dst[warp];
    const float* zr = z + (size_t)s * D;
    const float* qr = q + (size_t)d * D;
    float acc = 0.f;
#pragma unroll
    for (int c = 0; c < D / 32; c++) {
        int f = lane + 32 * c;
        acc += zr[f] * qr[f];
    }
#pragma unroll
    for (int o = 16; o > 0; o >>= 1) acc += __shfl_xor_sync(0xffffffffu, acc, o);
    if (lane == 0) atomicAdd(&pos[d], acc * TEMP_INV);
}

// fused GEMM + exp + rowsum: out[i] += sum_j exp(2 * A_i . B_j)
// 128x128x32 tiles, 8x8 micro, grid (ceil(n/128), NSPLIT)
__global__ __launch_bounds__(256) void negsum_k(
    const float* __restrict__ A, const float* __restrict__ B,
    float* __restrict__ out, int n) {
    __shared__ float As[32][128];
    __shared__ float Bs[32][128];
    int tid = threadIdx.x;
    int tx = tid & 15, ty = tid >> 4;
    int i0 = blockIdx.x * 128;
    int nJT = (n + 127) / 128;
    float rowsum[8] = {};
    for (int jt = blockIdx.y; jt < nJT; jt += gridDim.y) {
        int j0 = jt * 128;
        float acc[8][8] = {};
        for (int k0 = 0; k0 < D; k0 += 32) {
#pragma unroll
            for (int t = 0; t < 16; t++) {
                int idx = t * 256 + tid;
                int r = idx >> 5, kk = idx & 31;
                As[kk][r] = (i0 + r < n) ? A[(size_t)(i0 + r) * D + k0 + kk] : 0.f;
            }
#pragma unroll
            for (int t = 0; t < 16; t++) {
                int idx = t * 256 + tid;
                int r = idx >> 5, kk = idx & 31;
                Bs[kk][r] = (j0 + r < n) ? B[(size_t)(j0 + r) * D + k0 + kk] : 0.f;
            }
            __syncthreads();
#pragma unroll
            for (int kk = 0; kk < 32; kk++) {
                float a[8], b[8];
                *(float4*)&a[0] = *(float4*)&As[kk][ty * 8];
                *(float4*)&a[4] = *(float4*)&As[kk][ty * 8 + 4];
                *(float4*)&b[0] = *(float4*)&Bs[kk][tx * 8];
                *(float4*)&b[4] = *(float4*)&Bs[kk][tx * 8 + 4];
#pragma unroll
                for (int ri = 0; ri < 8; ri++)
#pragma unroll
                    for (int rj = 0; rj < 8; rj++) acc[ri][rj] += a[ri] * b[rj];
            }
            __syncthreads();
        }
#pragma unroll
        for (int rj = 0; rj < 8; rj++) {
            if (j0 + tx * 8 + rj < n) {
#pragma unroll
                for (int ri = 0; ri < 8; ri++)
                    rowsum[ri] += __expf(acc[ri][rj] * TEMP_INV);
            }
        }
    }
    __syncthreads();
    float* red = &As[0][0];  // 128*16 floats
#pragma unroll
    for (int ri = 0; ri < 8; ri++) red[(ty * 8 + ri) * 16 + tx] = rowsum[ri];
    __syncthreads();
    if (tid < 128) {
        float s = 0.f;
#pragma unroll
        for (int c = 0; c < 16; c++) s += red[tid * 16 + c];
        if (i0 + tid < n) atomicAdd(&out[i0 + tid], s);
    }
}

__global__ void mneg_k(const float* __restrict__ s1, const float* __restrict__ s2,
                       const int* __restrict__ src, const int* __restrict__ dst,
                       float* neg, int e) {
    int i = blockIdx.x * blockDim.x + threadIdx.x;
    if (i < e) {
        float m = logf(s1[dst[i]] + LAM * s2[src[i]]);
        atomicAdd(&neg[dst[i]], m);
    }
}

__global__ void loss_k(const float* __restrict__ pos, const float* __restrict__ neg,
                       const float* __restrict__ din, float* out, int n) {
    __shared__ float sm[256];
    float s = 0.f;
    for (int i = blockIdx.x * blockDim.x + threadIdx.x; i < n; i += gridDim.x * blockDim.x)
        s += (neg[i] - pos[i]) / din[i];
    sm[threadIdx.x] = s;
    __syncthreads();
    for (int o = 128; o > 0; o >>= 1) {
        if (threadIdx.x < o) sm[threadIdx.x] += sm[threadIdx.x + o];
        __syncthreads();
    }
    if (threadIdx.x == 0) atomicAdd(out, sm[0] / n);
}

// ------------------------------ launcher ------------------------------
static float* sym(const void* s) {
    void* p = nullptr;
    cudaGetSymbolAddress(&p, s);
    return (float*)p;
}

extern "C" void kernel_launch(void* const* d_in, const int* in_sizes, int n_in,
                              void* d_out, int out_size) {
    const float* feat  = (const float*)d_in[0];
    const float* W1    = (const float*)d_in[1];
    const float* b1    = (const float*)d_in[2];
    const float* W2    = (const float*)d_in[3];
    const float* b2    = (const float*)d_in[4];
    const float* Wt1   = (const float*)d_in[5];
    const float* bt1   = (const float*)d_in[6];
    const float* gamma = (const float*)d_in[7];
    const float* beta  = (const float*)d_in[8];
    const float* Wt2   = (const float*)d_in[9];
    const float* bt2   = (const float*)d_in[10];
    const float* Wp    = (const float*)d_in[11];
    const float* bp    = (const float*)d_in[12];
    const int*   src   = (const int*)d_in[13];
    const int*   dst   = (const int*)d_in[14];

    const int IN = 512;
    int n = in_sizes[0] / IN;
    int e = in_sizes[13];

    float* bufA = sym(g_bufA);
    float* bufB = sym(g_bufB);
    float* tbuf = sym(g_t);
    float* hbuf = sym(g_h);
    float* zbuf = sym(g_z);
    float* qbuf = sym(g_q);
    float* dout = sym(g_degout);
    float* din  = sym(g_degin);
    float* musum = sym(g_musum);
    float* varsum = sym(g_varsum);
    float* s1 = sym(g_s1);
    float* s2 = sym(g_s2);
    float* pos = sym(g_pos);
    float* neg = sym(g_neg);
    float* out = (float*)d_out;

    int nd = n * D;
    dim3 gemm_grid((n + 63) / 64, D / 64);
    int edge_warp_blocks = (e * 32 + 255) / 256;

    // degrees
    zero_k<<<(n + 255) / 256, 256>>>(dout, n);
    zero_k<<<(n + 255) / 256, 256>>>(din, n);
    degree_k<<<(e + 255) / 256, 256>>>(src, dst, dout, din, e);

    // GCN layer 1: xw1 = feat@W1 ; agg ; +b1 relu
    sgemm_k<<<gemm_grid, 256>>>(feat, W1, nullptr, bufA, n, IN, D, 0);
    zero_k<<<(nd + 255) / 256, 256>>>(bufB, nd);
    scatter_k<<<edge_warp_blocks, 256>>>(bufA, src, dst, dout, din, bufB, e);
    biasact_k<<<(nd + 255) / 256, 256>>>(bufB, b1, n, 1);

    // GCN layer 2: xw2 = h1@W2 ; agg ; +b2
    sgemm_k<<<gemm_grid, 256>>>(bufB, W2, nullptr, bufA, n, D, D, 0);
    zero_k<<<(nd + 255) / 256, 256>>>(hbuf, nd);
    scatter_k<<<edge_warp_blocks, 256>>>(bufA, src, dst, dout, din, hbuf, e);
    biasact_k<<<(nd + 255) / 256, 256>>>(hbuf, b2, n, 0);

    // target MLP: t = feat@Wt1+bt1 ; BN ; relu ; trans = t@Wt2+bt2 ; p = trans@Wp+bp
    sgemm_k<<<gemm_grid, 256>>>(feat, Wt1, bt1, tbuf, n, IN, D, 0);
    zero_k<<<1, 256>>>(musum, D);
    zero_k<<<1, 256>>>(varsum, D);
    bnstat_k<<<100, 256>>>(tbuf, musum, varsum, n);
    bnapply_k<<<(nd + 255) / 256, 256>>>(tbuf, musum, varsum, gamma, beta, n);
    sgemm_k<<<gemm_grid, 256>>>(tbuf, Wt2, bt2, bufA, n, D, D, 0);   // trans
    sgemm_k<<<gemm_grid, 256>>>(bufA, Wp, bp, bufB, n, D, D, 0);     // p

    // normalize
    norml_k<<<(n * 32 + 255) / 256, 256>>>(hbuf, zbuf, n);
    norml_k<<<(n * 32 + 255) / 256, 256>>>(bufB, qbuf, n);

    // pos
    zero_k<<<(n + 255) / 256, 256>>>(pos, n);
    pos_k<<<edge_warp_blocks, 256>>>(zbuf, qbuf, src, dst, pos, e);

    // neg row sums (the heavy part)
    zero_k<<<(n + 255) / 256, 256>>>(s1, n);
    zero_k<<<(n + 255) / 256, 256>>>(s2, n);
    dim3 neg_grid((n + 127) / 128, 6);
    negsum_k<<<neg_grid, 256>>>(zbuf, zbuf, s1, n);
    negsum_k<<<neg_grid, 256>>>(zbuf, qbuf, s2, n);

    // m_e scatter + loss
    zero_k<<<(n + 255) / 256, 256>>>(neg, n);
    mneg_k<<<(e + 255) / 256, 256>>>(s1, s2, src, dst, neg, e);
    zero_k<<<1, 32>>>(out, out_size);
    loss_k<<<40, 256>>>(pos, neg, din, out, n);
}

// round 3
// speedup vs baseline: 7.0150x; 7.0150x over previous
#include <cuda_runtime.h>
#include <cuda_bf16.h>
#include <stdint.h>
#include <math.h>

#define NMAX 10240
#define D 256
#define TEMP_INV 2.0f
#define LAM 1e-3f
#define BN_EPS 1e-5f

// ------------------------------ scratch ------------------------------
__device__ __align__(16) float g_bufA[NMAX * D];   // xw1 -> xw2 -> trans
__device__ __align__(16) float g_bufB[NMAX * D];   // agg1/h1 -> p
__device__ __align__(16) float g_t[NMAX * D];      // t (BN path)
__device__ __align__(16) float g_h[NMAX * D];      // GCN output h
__device__ __align__(16) float g_z[NMAX * D];
__device__ __align__(16) float g_q[NMAX * D];
__device__ __align__(16) __nv_bfloat16 g_zh[NMAX * D];
__device__ __align__(16) __nv_bfloat16 g_qh[NMAX * D];
__device__ float g_degout[NMAX];
__device__ float g_degin[NMAX];
__device__ float g_musum[D];
__device__ float g_varsum[D];
__device__ float g_s1[NMAX];
__device__ float g_s2[NMAX];
__device__ float g_pos[NMAX];
__device__ float g_neg[NMAX];

// ------------------------------ kernels ------------------------------
__global__ void zero_k(float* p, int n) {
    int i = blockIdx.x * blockDim.x + threadIdx.x;
    if (i < n) p[i] = 0.f;
}

__global__ void degree_k(const int* __restrict__ src, const int* __restrict__ dst,
                         float* dout, float* din, int e) {
    int i = blockIdx.x * blockDim.x + threadIdx.x;
    if (i < e) {
        atomicAdd(&dout[src[i]], 1.f);
        atomicAdd(&din[dst[i]], 1.f);
    }
}

// C[M,Nc] = A[M,K] @ W[K,Nc] (+ bias) (+relu). 64x64 tiles, BK=16, 4x4 micro.
__global__ __launch_bounds__(256) void sgemm_k(
    const float* __restrict__ A, const float* __restrict__ W,
    const float* __restrict__ bias, float* __restrict__ C,
    int M, int K, int Nc, int relu) {
    __shared__ float As[16][64];
    __shared__ float Ws[16][64];
    int tid = threadIdx.x;
    int tx = tid & 15, ty = tid >> 4;
    int m0 = blockIdx.x * 64, n0 = blockIdx.y * 64;
    float acc[4][4] = {};
    for (int k0 = 0; k0 < K; k0 += 16) {
        {
            int row = tid >> 2, kk = (tid & 3) * 4;
            float4 v = make_float4(0.f, 0.f, 0.f, 0.f);
            if (m0 + row < M)
                v = *(const float4*)&A[(size_t)(m0 + row) * K + k0 + kk];
            As[kk + 0][row] = v.x; As[kk + 1][row] = v.y;
            As[kk + 2][row] = v.z; As[kk + 3][row] = v.w;
            int kr = tid >> 4, c = (tid & 15) * 4;
            *(float4*)&Ws[kr][c] = *(const float4*)&W[(size_t)(k0 + kr) * Nc + n0 + c];
        }
        __syncthreads();
#pragma unroll
        for (int kk = 0; kk < 16; kk++) {
            float a[4], b[4];
            *(float4*)a = *(float4*)&As[kk][ty * 4];
            *(float4*)b = *(float4*)&Ws[kk][tx * 4];
#pragma unroll
            for (int ri = 0; ri < 4; ri++)
#pragma unroll
                for (int rj = 0; rj < 4; rj++) acc[ri][rj] += a[ri] * b[rj];
        }
        __syncthreads();
    }
#pragma unroll
    for (int ri = 0; ri < 4; ri++) {
        int r = m0 + ty * 4 + ri;
        if (r < M) {
#pragma unroll
            for (int rj = 0; rj < 4; rj++) {
                int c = n0 + tx * 4 + rj;
                float v = acc[ri][rj] + (bias ? bias[c] : 0.f);
                if (relu) v = fmaxf(v, 0.f);
                C[(size_t)r * Nc + c] = v;
            }
        }
    }
}

// per-edge: agg[dst] += xw[src] * norm_e  (one warp per edge, 256 feats)
__global__ void scatter_k(const float* __restrict__ xw, const int* __restrict__ src,
                          const int* __restrict__ dst, const float* __restrict__ dout,
                          const float* __restrict__ din, float* __restrict__ agg, int e) {
    int warp = (blockIdx.x * blockDim.x + threadIdx.x) >> 5;
    int lane = threadIdx.x & 31;
    if (warp >= e) return;
    int s = src[warp], d = dst[warp];
    float nm = rsqrtf(dout[s]) * rsqrtf(din[d]);
    const float* xs = xw + (size_t)s * D;
    float* ad = agg + (size_t)d * D;
#pragma unroll
    for (int c = 0; c < D / 32; c++) {
        int f = lane + 32 * c;
        atomicAdd(&ad[f], xs[f] * nm);
    }
}

__global__ void biasact_k(float* x, const float* __restrict__ b, int M, int relu) {
    int i = blockIdx.x * blockDim.x + threadIdx.x;
    if (i < M * D) {
        float v = x[i] + b[i & (D - 1)];
        if (relu) v = fmaxf(v, 0.f);
        x[i] = v;
    }
}

__global__ void bnstat_k(const float* __restrict__ t, float* musum, float* varsum, int M) {
    int col = threadIdx.x;
    int rpb = (M + gridDim.x - 1) / gridDim.x;
    int r0 = blockIdx.x * rpb;
    int r1 = min(r0 + rpb, M);
    float s = 0.f, s2 = 0.f;
    for (int r = r0; r < r1; r++) {
        float v = t[(size_t)r * D + col];
        s += v; s2 += v * v;
    }
    atomicAdd(&musum[col], s);
    atomicAdd(&varsum[col], s2);
}

__global__ void bnapply_k(float* t, const float* __restrict__ musum,
                          const float* __restrict__ varsum,
                          const float* __restrict__ gamma, const float* __restrict__ beta,
                          int M) {
    int i = blockIdx.x * blockDim.x + threadIdx.x;
    if (i < M * D) {
        int c = i & (D - 1);
        float mu = musum[c] / M;
        float var = varsum[c] / M - mu * mu;
        float v = (t[i] - mu) * (1.f / sqrtf(var + BN_EPS)) * gamma[c] + beta[c];
        t[i] = fmaxf(v, 0.f);  // relu fused
    }
}

// row-wise L2 normalize, one warp per row; also emit bf16 copy (zero-padded to Mpad rows)
__global__ void norml_k(const float* __restrict__ x, float* __restrict__ z,
                        __nv_bfloat16* __restrict__ zh, int M, int Mpad) {
    int row = (blockIdx.x * blockDim.x + threadIdx.x) >> 5;
    int lane = threadIdx.x & 31;
    if (row >= Mpad) return;
    __nv_bfloat16* hr = zh + (size_t)row * D;
    if (row >= M) {
#pragma unroll
        for (int c = 0; c < D / 32; c++) hr[lane + 32 * c] = __float2bfloat16(0.f);
        return;
    }
    const float* xr = x + (size_t)row * D;
    float s = 0.f;
#pragma unroll
    for (int c = 0; c < D / 32; c++) {
        float v = xr[lane + 32 * c];
        s += v * v;
    }
#pragma unroll
    for (int o = 16; o > 0; o >>= 1) s += __shfl_xor_sync(0xffffffffu, s, o);
    float inv = 1.f / fmaxf(sqrtf(s), 1e-12f);
    float* zr = z + (size_t)row * D;
#pragma unroll
    for (int c = 0; c < D / 32; c++) {
        int f = lane + 32 * c;
        float v = xr[f] * inv;
        zr[f] = v;
        hr[f] = __float2bfloat16(v);
    }
}

// pos: per-edge dot(z[src], q[dst])/TEMP -> atomicAdd pos[dst]
__global__ void pos_k(const float* __restrict__ z, const float* __restrict__ q,
                      const int* __restrict__ src, const int* __restrict__ dst,
                      float* pos, int e) {
    int warp = (blockIdx.x * blockDim.x + threadIdx.x) >> 5;
    int lane = threadIdx.x & 31;
    if (warp >= e) return;
    int s = src[warp], d = dst[warp];
    const float4* zr = (const float4*)(z + (size_t)s * D);
    const float4* qr = (const float4*)(q + (size_t)d * D);
    float acc = 0.f;
#pragma unroll
    for (int c = 0; c < D / 128; c++) {
        int f = lane + 32 * c;
        float4 a = zr[f], b = qr[f];
        acc += a.x * b.x + a.y * b.y + a.z * b.z + a.w * b.w;
    }
#pragma unroll
    for (int o = 16; o > 0; o >>= 1) acc += __shfl_xor_sync(0xffffffffu, acc, o);
    if (lane == 0) atomicAdd(&pos[d], acc * TEMP_INV);
}

// ---------------- bf16 tensor-core fused GEMM+exp+rowsum ----------------
__device__ __forceinline__ void ldsm4(uint32_t addr, uint32_t& r0, uint32_t& r1,
                                      uint32_t& r2, uint32_t& r3) {
    asm volatile("ldmatrix.sync.aligned.m8n8.x4.shared.b16 {%0,%1,%2,%3}, [%4];"
                 : "=r"(r0), "=r"(r1), "=r"(r2), "=r"(r3) : "r"(addr));
}

__device__ __forceinline__ void mma16816(float* c, const uint32_t* a,
                                         uint32_t b0, uint32_t b1) {
    asm volatile(
        "mma.sync.aligned.m16n8k16.row.col.f32.bf16.bf16.f32 "
        "{%0,%1,%2,%3}, {%4,%5,%6,%7}, {%8,%9}, {%0,%1,%2,%3};"
        : "+f"(c[0]), "+f"(c[1]), "+f"(c[2]), "+f"(c[3])
        : "r"(a[0]), "r"(a[1]), "r"(a[2]), "r"(a[3]), "r"(b0), "r"(b1));
}

// out[i] += sum_j exp(2 * A_i . B_j); A,B bf16 [npad, 256], zero-padded rows.
// CTA tile 128(i) x 128(j), 8 warps as 4x2, warp tile 32x64, k-step 64 in smem.
__global__ __launch_bounds__(256, 2) void negmma_k(
    const __nv_bfloat16* __restrict__ A, const __nv_bfloat16* __restrict__ B,
    float* __restrict__ out, int n, int nJT) {
    __shared__ __nv_bfloat16 sA[128 * 64];
    __shared__ __nv_bfloat16 sB[128 * 64];
    int tid = threadIdx.x;
    int lane = tid & 31, warp = tid >> 5;
    int wi = warp >> 1, wj = warp & 1;
    int i0 = blockIdx.x * 128;

    uint32_t sAu = (uint32_t)__cvta_generic_to_shared(sA);
    uint32_t sBu = (uint32_t)__cvta_generic_to_shared(sB);

    // per-lane A/B ldmatrix swizzled address offsets (row*128 + swizzled chunk*16)
    int a_row = (lane & 15);                                // within 16-row tile
    int a_chsel = (lane >> 4);                              // 0/1 -> +16B
    int b_row = (lane & 7) + ((lane >> 4) & 1) * 8;         // within 16-row tile
    int b_chsel = ((lane >> 3) & 1);

    float rs[2][2] = {{0.f, 0.f}, {0.f, 0.f}};  // [mt][lo/hi 8-rows]

    for (int jt = blockIdx.y; jt < nJT; jt += gridDim.y) {
        int j0 = jt * 128;
        float acc[2][8][4];
#pragma unroll
        for (int x = 0; x < 2; x++)
#pragma unroll
            for (int y = 0; y < 8; y++)
#pragma unroll
                for (int v = 0; v < 4; v++) acc[x][y][v] = 0.f;

        for (int k0 = 0; k0 < D; k0 += 64) {
            // load 128x64 bf16 tiles (16KB each), SW128-style chunk swizzle
#pragma unroll
            for (int t = 0; t < 4; t++) {
                int c = tid + t * 256;       // 0..1023 16B-chunks
                int row = c >> 3, ch = c & 7;
                uint32_t off = (uint32_t)(row * 128 + ((ch ^ (row & 7)) << 4));
                uint4 va = *(const uint4*)(A + (size_t)(i0 + row) * D + k0 + ch * 8);
                *(uint4*)((char*)sA + off) = va;
                uint4 vb = *(const uint4*)(B + (size_t)(j0 + row) * D + k0 + ch * 8);
                *(uint4*)((char*)sB + off) = vb;
            }
            __syncthreads();
#pragma unroll
            for (int ks = 0; ks < 4; ks++) {
                // A fragments: 2 m-tiles of 16 rows
                uint32_t afr[2][4];
#pragma unroll
                for (int mt = 0; mt < 2; mt++) {
                    int row = wi * 32 + mt * 16 + a_row;
                    int ch = ks * 2 + a_chsel;             // 16B chunk within row
                    uint32_t addr = sAu + (uint32_t)(row * 128 +
                                     ((ch ^ (row & 7)) << 4));
                    ldsm4(addr, afr[mt][0], afr[mt][1], afr[mt][2], afr[mt][3]);
                }
                // B fragments: 4 n-tile pairs (16 j's per ldmatrix.x4)
#pragma unroll
                for (int p = 0; p < 4; p++) {
                    int nrow = wj * 64 + p * 16 + b_row;
                    int ch = ks * 2 + b_chsel;
                    uint32_t addr = sBu + (uint32_t)(nrow * 128 +
                                     ((ch ^ (nrow & 7)) << 4));
                    uint32_t bf0, bf1, bf2, bf3;
                    ldsm4(addr, bf0, bf1, bf2, bf3);
#pragma unroll
                    for (int mt = 0; mt < 2; mt++) {
                        mma16816(acc[mt][2 * p], afr[mt], bf0, bf1);
                        mma16816(acc[mt][2 * p + 1], afr[mt], bf2, bf3);
                    }
                }
            }
            __syncthreads();
        }
        // epilogue: exp + masked row partial-sums into registers
#pragma unroll
        for (int mt = 0; mt < 2; mt++) {
#pragma unroll
            for (int nt = 0; nt < 8; nt++) {
                int j = j0 + wj * 64 + nt * 8 + (lane & 3) * 2;
                float e0 = (j < n) ? __expf(acc[mt][nt][0] * TEMP_INV) : 0.f;
                float e1 = (j + 1 < n) ? __expf(acc[mt][nt][1] * TEMP_INV) : 0.f;
                float e2 = (j < n) ? __expf(acc[mt][nt][2] * TEMP_INV) : 0.f;
                float e3 = (j + 1 < n) ? __expf(acc[mt][nt][3] * TEMP_INV) : 0.f;
                rs[mt][0] += e0 + e1;
                rs[mt][1] += e2 + e3;
            }
        }
    }
    // quad reduce (lanes sharing a row differ in bits 0..1), then atomic flush
#pragma unroll
    for (int mt = 0; mt < 2; mt++) {
#pragma unroll
        for (int h = 0; h < 2; h++) {
            float v = rs[mt][h];
            v += __shfl_xor_sync(0xffffffffu, v, 1);
            v += __shfl_xor_sync(0xffffffffu, v, 2);
            if ((lane & 3) == 0) {
                int i = i0 + wi * 32 + mt * 16 + h * 8 + (lane >> 2);
                if (i < n) atomicAdd(&out[i], v);
            }
        }
    }
}

__global__ void mneg_k(const float* __restrict__ s1, const float* __restrict__ s2,
                       const int* __restrict__ src, const int* __restrict__ dst,
                       float* neg, int e) {
    int i = blockIdx.x * blockDim.x + threadIdx.x;
    if (i < e) {
        float m = logf(s1[dst[i]] + LAM * s2[src[i]]);
        atomicAdd(&neg[dst[i]], m);
    }
}

__global__ void loss_k(const float* __restrict__ pos, const float* __restrict__ neg,
                       const float* __restrict__ din, float* out, int n) {
    __shared__ float sm[256];
    float s = 0.f;
    for (int i = blockIdx.x * blockDim.x + threadIdx.x; i < n; i += gridDim.x * blockDim.x)
        s += (neg[i] - pos[i]) / din[i];
    sm[threadIdx.x] = s;
    __syncthreads();
    for (int o = 128; o > 0; o >>= 1) {
        if (threadIdx.x < o) sm[threadIdx.x] += sm[threadIdx.x + o];
        __syncthreads();
    }
    if (threadIdx.x == 0) atomicAdd(out, sm[0] / n);
}

// ------------------------------ launcher ------------------------------
static float* symf(const void* s) {
    void* p = nullptr;
    cudaGetSymbolAddress(&p, s);
    return (float*)p;
}
static __nv_bfloat16* symh(const void* s) {
    void* p = nullptr;
    cudaGetSymbolAddress(&p, s);
    return (__nv_bfloat16*)p;
}

extern "C" void kernel_launch(void* const* d_in, const int* in_sizes, int n_in,
                              void* d_out, int out_size) {
    const float* feat  = (const float*)d_in[0];
    const float* W1    = (const float*)d_in[1];
    const float* b1    = (const float*)d_in[2];
    const float* W2    = (const float*)d_in[3];
    const float* b2    = (const float*)d_in[4];
    const float* Wt1   = (const float*)d_in[5];
    const float* bt1   = (const float*)d_in[6];
    const float* gamma = (const float*)d_in[7];
    const float* beta  = (const float*)d_in[8];
    const float* Wt2   = (const float*)d_in[9];
    const float* bt2   = (const float*)d_in[10];
    const float* Wp    = (const float*)d_in[11];
    const float* bp    = (const float*)d_in[12];
    const int*   src   = (const int*)d_in[13];
    const int*   dst   = (const int*)d_in[14];

    const int IN = 512;
    int n = in_sizes[0] / IN;
    int e = in_sizes[13];
    int nTI = (n + 127) / 128;   // 128-row tiles
    int npad = nTI * 128;

    float* bufA = symf(g_bufA);
    float* bufB = symf(g_bufB);
    float* tbuf = symf(g_t);
    float* hbuf = symf(g_h);
    float* zbuf = symf(g_z);
    float* qbuf = symf(g_q);
    __nv_bfloat16* zh = symh(g_zh);
    __nv_bfloat16* qh = symh(g_qh);
    float* dout = symf(g_degout);
    float* din  = symf(g_degin);
    float* musum = symf(g_musum);
    float* varsum = symf(g_varsum);
    float* s1 = symf(g_s1);
    float* s2 = symf(g_s2);
    float* pos = symf(g_pos);
    float* neg = symf(g_neg);
    float* out = (float*)d_out;

    int nd = n * D;
    dim3 gemm_grid((n + 63) / 64, D / 64);
    int edge_warp_blocks = (e * 32 + 255) / 256;

    // degrees
    zero_k<<<(n + 255) / 256, 256>>>(dout, n);
    zero_k<<<(n + 255) / 256, 256>>>(din, n);
    degree_k<<<(e + 255) / 256, 256>>>(src, dst, dout, din, e);

    // GCN layer 1
    sgemm_k<<<gemm_grid, 256>>>(feat, W1, nullptr, bufA, n, IN, D, 0);
    zero_k<<<(nd + 255) / 256, 256>>>(bufB, nd);
    scatter_k<<<edge_warp_blocks, 256>>>(bufA, src, dst, dout, din, bufB, e);
    biasact_k<<<(nd + 255) / 256, 256>>>(bufB, b1, n, 1);

    // GCN layer 2
    sgemm_k<<<gemm_grid, 256>>>(bufB, W2, nullptr, bufA, n, D, D, 0);
    zero_k<<<(nd + 255) / 256, 256>>>(hbuf, nd);
    scatter_k<<<edge_warp_blocks, 256>>>(bufA, src, dst, dout, din, hbuf, e);
    biasact_k<<<(nd + 255) / 256, 256>>>(hbuf, b2, n, 0);

    // target MLP
    sgemm_k<<<gemm_grid, 256>>>(feat, Wt1, bt1, tbuf, n, IN, D, 0);
    zero_k<<<1, 256>>>(musum, D);
    zero_k<<<1, 256>>>(varsum, D);
    bnstat_k<<<100, 256>>>(tbuf, musum, varsum, n);
    bnapply_k<<<(nd + 255) / 256, 256>>>(tbuf, musum, varsum, gamma, beta, n);
    sgemm_k<<<gemm_grid, 256>>>(tbuf, Wt2, bt2, bufA, n, D, D, 0);   // trans
    sgemm_k<<<gemm_grid, 256>>>(bufA, Wp, bp, bufB, n, D, D, 0);     // p

    // normalize (+ bf16 copies, zero-padded to npad rows)
    norml_k<<<(npad * 32 + 255) / 256, 256>>>(hbuf, zbuf, zh, n, npad);
    norml_k<<<(npad * 32 + 255) / 256, 256>>>(bufB, qbuf, qh, n, npad);

    // pos
    zero_k<<<(n + 255) / 256, 256>>>(pos, n);
    pos_k<<<edge_warp_blocks, 256>>>(zbuf, qbuf, src, dst, pos, e);

    // neg row sums on tensor cores
    zero_k<<<(n + 255) / 256, 256>>>(s1, n);
    zero_k<<<(n + 255) / 256, 256>>>(s2, n);
    dim3 neg_grid(nTI, 8);
    negmma_k<<<neg_grid, 256>>>(zh, zh, s1, n, nTI);
    negmma_k<<<neg_grid, 256>>>(zh, qh, s2, n, nTI);

    // m_e scatter + loss
    zero_k<<<(n + 255) / 256, 256>>>(neg, n);
    mneg_k<<<(e + 255) / 256, 256>>>(s1, s2, src, dst, neg, e);
    zero_k<<<1, 32>>>(out, out_size);
    loss_k<<<40, 256>>>(pos, neg, din, out, n);
}

// round 4
// speedup vs baseline: 9.0050x; 1.2837x over previous
#include <cuda_runtime.h>
#include <cuda_bf16.h>
#include <stdint.h>
#include <math.h>

#define NMAX 10240
#define D 256
#define INMAX 512
#define TEMP_INV 2.0f
#define LAM 1e-3f
#define BN_EPS 1e-5f

// ------------------------------ scratch ------------------------------
__device__ __align__(16) float g_bufA[NMAX * D];   // xw1 -> xw2
__device__ __align__(16) float g_bufB[NMAX * D];   // agg1/h1 -> p
__device__ __align__(16) float g_t[NMAX * D];      // t (BN path)
__device__ __align__(16) float g_h[NMAX * D];      // GCN output h
__device__ __align__(16) float g_z[NMAX * D];
__device__ __align__(16) float g_q[NMAX * D];
__device__ __align__(16) __nv_bfloat16 g_featb[NMAX * INMAX];
__device__ __align__(16) __nv_bfloat16 g_h1b[NMAX * D];
__device__ __align__(16) __nv_bfloat16 g_tb[NMAX * D];
__device__ __align__(16) __nv_bfloat16 g_transb[NMAX * D];
__device__ __align__(16) __nv_bfloat16 g_zh[NMAX * D];
__device__ __align__(16) __nv_bfloat16 g_qh[NMAX * D];
__device__ __align__(16) __nv_bfloat16 g_W1b[INMAX * D];   // [N=256, K=512]
__device__ __align__(16) __nv_bfloat16 g_W2b[D * D];
__device__ __align__(16) __nv_bfloat16 g_Wt1b[INMAX * D];
__device__ __align__(16) __nv_bfloat16 g_Wt2b[D * D];
__device__ __align__(16) __nv_bfloat16 g_Wpb[D * D];
__device__ float g_degout[NMAX];
__device__ float g_degin[NMAX];
__device__ float g_musum[D];
__device__ float g_varsum[D];
__device__ float g_s1[NMAX];
__device__ float g_s2[NMAX];
__device__ float g_pos[NMAX];
__device__ float g_neg[NMAX];

// ------------------------------ small kernels ------------------------------
__global__ void zero_k(float* p, int n) {
    int i = blockIdx.x * blockDim.x + threadIdx.x;
    if (i < n) p[i] = 0.f;
}

// fp32 -> bf16, zero-pad beyond n up to ntot
__global__ void f2b_k(const float* __restrict__ x, __nv_bfloat16* __restrict__ y,
                      int n, int ntot) {
    int i = blockIdx.x * blockDim.x + threadIdx.x;
    if (i < ntot) y[i] = __float2bfloat16(i < n ? x[i] : 0.f);
}

// transpose-convert weight W[K,N] (row-major) -> Wt[N,K] bf16
__global__ void wconv_k(const float* __restrict__ W, __nv_bfloat16* __restrict__ Wt,
                        int K, int N) {
    int i = blockIdx.x * blockDim.x + threadIdx.x;
    if (i < K * N) {
        int k = i / N, n = i % N;
        Wt[n * K + k] = __float2bfloat16(W[i]);
    }
}

__global__ void zerohtail_k(__nv_bfloat16* p, int from, int to) {
    int i = from + blockIdx.x * blockDim.x + threadIdx.x;
    if (i < to) p[i] = __float2bfloat16(0.f);
}

__global__ void degree_k(const int* __restrict__ src, const int* __restrict__ dst,
                         float* dout, float* din, int e) {
    int i = blockIdx.x * blockDim.x + threadIdx.x;
    if (i < e) {
        atomicAdd(&dout[src[i]], 1.f);
        atomicAdd(&din[dst[i]], 1.f);
    }
}

// per-edge: agg[dst] += xw[src] * norm_e  (one warp per edge, v4 reductions)
__global__ void scatter_k(const float* __restrict__ xw, const int* __restrict__ src,
                          const int* __restrict__ dst, const float* __restrict__ dout,
                          const float* __restrict__ din, float* __restrict__ agg, int e) {
    int warp = (blockIdx.x * blockDim.x + threadIdx.x) >> 5;
    int lane = threadIdx.x & 31;
    if (warp >= e) return;
    int s = src[warp], d = dst[warp];
    float nm = rsqrtf(dout[s]) * rsqrtf(din[d]);
    const float4* xs = (const float4*)(xw + (size_t)s * D);
    float4* ad = (float4*)(agg + (size_t)d * D);
#pragma unroll
    for (int c = 0; c < D / 128; c++) {
        int f = lane + 32 * c;  // float4 index 0..63
        float4 v = xs[f];
        asm volatile("red.global.add.v4.f32 [%0], {%1,%2,%3,%4};"
                     :: "l"(ad + f), "f"(v.x * nm), "f"(v.y * nm),
                        "f"(v.z * nm), "f"(v.w * nm) : "memory");
    }
}

// x += bias (+relu); optional bf16 emission
__global__ void biasact_k(float* x, const float* __restrict__ b,
                          __nv_bfloat16* xh, int M, int relu) {
    int i = blockIdx.x * blockDim.x + threadIdx.x;
    if (i < M * D) {
        float v = x[i] + b[i & (D - 1)];
        if (relu) v = fmaxf(v, 0.f);
        x[i] = v;
        if (xh) xh[i] = __float2bfloat16(v);
    }
}

__global__ void bnstat_k(const float* __restrict__ t, float* musum, float* varsum, int M) {
    int col = threadIdx.x;
    int rpb = (M + gridDim.x - 1) / gridDim.x;
    int r0 = blockIdx.x * rpb;
    int r1 = min(r0 + rpb, M);
    float s = 0.f, s2 = 0.f;
    for (int r = r0; r < r1; r++) {
        float v = t[(size_t)r * D + col];
        s += v; s2 += v * v;
    }
    atomicAdd(&musum[col], s);
    atomicAdd(&varsum[col], s2);
}

// BN + relu fused; emits bf16
__global__ void bnapply_k(const float* __restrict__ t, const float* __restrict__ musum,
                          const float* __restrict__ varsum,
                          const float* __restrict__ gamma, const float* __restrict__ beta,
                          __nv_bfloat16* th, int M) {
    int i = blockIdx.x * blockDim.x + threadIdx.x;
    if (i < M * D) {
        int c = i & (D - 1);
        float mu = musum[c] / M;
        float var = varsum[c] / M - mu * mu;
        float v = (t[i] - mu) * rsqrtf(var + BN_EPS) * gamma[c] + beta[c];
        th[i] = __float2bfloat16(fmaxf(v, 0.f));
    }
}

// row-wise L2 normalize, one warp per row; emits fp32 + bf16 (zero-padded rows)
__global__ void norml_k(const float* __restrict__ x, float* __restrict__ z,
                        __nv_bfloat16* __restrict__ zh, int M, int Mpad) {
    int row = (blockIdx.x * blockDim.x + threadIdx.x) >> 5;
    int lane = threadIdx.x & 31;
    if (row >= Mpad) return;
    __nv_bfloat16* hr = zh + (size_t)row * D;
    if (row >= M) {
#pragma unroll
        for (int c = 0; c < D / 32; c++) hr[lane + 32 * c] = __float2bfloat16(0.f);
        return;
    }
    const float* xr = x + (size_t)row * D;
    float s = 0.f;
#pragma unroll
    for (int c = 0; c < D / 32; c++) {
        float v = xr[lane + 32 * c];
        s += v * v;
    }
#pragma unroll
    for (int o = 16; o > 0; o >>= 1) s += __shfl_xor_sync(0xffffffffu, s, o);
    float inv = 1.f / fmaxf(sqrtf(s), 1e-12f);
    float* zr = z + (size_t)row * D;
#pragma unroll
    for (int c = 0; c < D / 32; c++) {
        int f = lane + 32 * c;
        float v = xr[f] * inv;
        zr[f] = v;
        hr[f] = __float2bfloat16(v);
    }
}

// pos: per-edge dot(z[src], q[dst])/TEMP -> atomicAdd pos[dst]
__global__ void pos_k(const float* __restrict__ z, const float* __restrict__ q,
                      const int* __restrict__ src, const int* __restrict__ dst,
                      float* pos, int e) {
    int warp = (blockIdx.x * blockDim.x + threadIdx.x) >> 5;
    int lane = threadIdx.x & 31;
    if (warp >= e) return;
    int s = src[warp], d = dst[warp];
    const float4* zr = (const float4*)(z + (size_t)s * D);
    const float4* qr = (const float4*)(q + (size_t)d * D);
    float acc = 0.f;
#pragma unroll
    for (int c = 0; c < D / 128; c++) {
        int f = lane + 32 * c;
        float4 a = zr[f], b = qr[f];
        acc += a.x * b.x + a.y * b.y + a.z * b.z + a.w * b.w;
    }
#pragma unroll
    for (int o = 16; o > 0; o >>= 1) acc += __shfl_xor_sync(0xffffffffu, acc, o);
    if (lane == 0) atomicAdd(&pos[d], acc * TEMP_INV);
}

// ---------------- shared mma helpers ----------------
__device__ __forceinline__ void ldsm4(uint32_t addr, uint32_t& r0, uint32_t& r1,
                                      uint32_t& r2, uint32_t& r3) {
    asm volatile("ldmatrix.sync.aligned.m8n8.x4.shared.b16 {%0,%1,%2,%3}, [%4];"
                 : "=r"(r0), "=r"(r1), "=r"(r2), "=r"(r3) : "r"(addr));
}

__device__ __forceinline__ void mma16816(float* c, const uint32_t* a,
                                         uint32_t b0, uint32_t b1) {
    asm volatile(
        "mma.sync.aligned.m16n8k16.row.col.f32.bf16.bf16.f32 "
        "{%0,%1,%2,%3}, {%4,%5,%6,%7}, {%8,%9}, {%0,%1,%2,%3};"
        : "+f"(c[0]), "+f"(c[1]), "+f"(c[2]), "+f"(c[3])
        : "r"(a[0]), "r"(a[1]), "r"(a[2]), "r"(a[3]), "r"(b0), "r"(b1));
}

// ---------------- bf16 tensor GEMM: C[M,256] = A[Mpad,K] @ Wt[256,K]^T ----------------
// CTA tile 128x128, 8 warps 4x2, warp 32x64. A zero-padded to Mpad rows.
__global__ __launch_bounds__(256, 2) void gemm_bf16_k(
    const __nv_bfloat16* __restrict__ A, const __nv_bfloat16* __restrict__ Wt,
    const float* __restrict__ bias, float* __restrict__ Cf,
    __nv_bfloat16* __restrict__ Ch, int M, int K, int relu) {
    __shared__ __nv_bfloat16 sA[128 * 64];
    __shared__ __nv_bfloat16 sB[128 * 64];
    int tid = threadIdx.x;
    int lane = tid & 31, warp = tid >> 5;
    int wi = warp >> 1, wj = warp & 1;
    int i0 = blockIdx.x * 128, j0 = blockIdx.y * 128;

    uint32_t sAu = (uint32_t)__cvta_generic_to_shared(sA);
    uint32_t sBu = (uint32_t)__cvta_generic_to_shared(sB);

    int a_row = (lane & 15);
    int a_chsel = (lane >> 4);
    int b_row = (lane & 7) + ((lane >> 4) & 1) * 8;
    int b_chsel = ((lane >> 3) & 1);

    float acc[2][8][4];
#pragma unroll
    for (int x = 0; x < 2; x++)
#pragma unroll
        for (int y = 0; y < 8; y++)
#pragma unroll
            for (int v = 0; v < 4; v++) acc[x][y][v] = 0.f;

    for (int k0 = 0; k0 < K; k0 += 64) {
#pragma unroll
        for (int t = 0; t < 4; t++) {
            int c = tid + t * 256;           // 0..1023 16B-chunks
            int row = c >> 3, ch = c & 7;
            uint32_t off = (uint32_t)(row * 128 + ((ch ^ (row & 7)) << 4));
            uint4 va = *(const uint4*)(A + (size_t)(i0 + row) * K + k0 + ch * 8);
            *(uint4*)((char*)sA + off) = va;
            uint4 vb = *(const uint4*)(Wt + (size_t)(j0 + row) * K + k0 + ch * 8);
            *(uint4*)((char*)sB + off) = vb;
        }
        __syncthreads();
#pragma unroll
        for (int ks = 0; ks < 4; ks++) {
            uint32_t afr[2][4];
#pragma unroll
            for (int mt = 0; mt < 2; mt++) {
                int row = wi * 32 + mt * 16 + a_row;
                int ch = ks * 2 + a_chsel;
                uint32_t addr = sAu + (uint32_t)(row * 128 + ((ch ^ (row & 7)) << 4));
                ldsm4(addr, afr[mt][0], afr[mt][1], afr[mt][2], afr[mt][3]);
            }
#pragma unroll
            for (int p = 0; p < 4; p++) {
                int nrow = wj * 64 + p * 16 + b_row;
                int ch = ks * 2 + b_chsel;
                uint32_t addr = sBu + (uint32_t)(nrow * 128 + ((ch ^ (nrow & 7)) << 4));
                uint32_t bf0, bf1, bf2, bf3;
                ldsm4(addr, bf0, bf1, bf2, bf3);
#pragma unroll
                for (int mt = 0; mt < 2; mt++) {
                    mma16816(acc[mt][2 * p], afr[mt], bf0, bf1);
                    mma16816(acc[mt][2 * p + 1], afr[mt], bf2, bf3);
                }
            }
        }
        __syncthreads();
    }
    // epilogue: bias, relu, store fp32 and/or bf16
#pragma unroll
    for (int mt = 0; mt < 2; mt++) {
        int r0 = i0 + wi * 32 + mt * 16 + (lane >> 2);
#pragma unroll
        for (int nt = 0; nt < 8; nt++) {
            int col = j0 + wj * 64 + nt * 8 + (lane & 3) * 2;
            float b0 = bias ? bias[col] : 0.f;
            float b1 = bias ? bias[col + 1] : 0.f;
            float v0 = acc[mt][nt][0] + b0, v1 = acc[mt][nt][1] + b1;
            float v2 = acc[mt][nt][2] + b0, v3 = acc[mt][nt][3] + b1;
            if (relu) {
                v0 = fmaxf(v0, 0.f); v1 = fmaxf(v1, 0.f);
                v2 = fmaxf(v2, 0.f); v3 = fmaxf(v3, 0.f);
            }
            if (r0 < M) {
                if (Cf) { Cf[(size_t)r0 * D + col] = v0; Cf[(size_t)r0 * D + col + 1] = v1; }
                if (Ch) {
                    Ch[(size_t)r0 * D + col] = __float2bfloat16(v0);
                    Ch[(size_t)r0 * D + col + 1] = __float2bfloat16(v1);
                }
            }
            int r1 = r0 + 8;
            if (r1 < M) {
                if (Cf) { Cf[(size_t)r1 * D + col] = v2; Cf[(size_t)r1 * D + col + 1] = v3; }
                if (Ch) {
                    Ch[(size_t)r1 * D + col] = __float2bfloat16(v2);
                    Ch[(size_t)r1 * D + col + 1] = __float2bfloat16(v3);
                }
            }
        }
    }
}

// ---------------- bf16 fused GEMM+exp+rowsum ----------------
__global__ __launch_bounds__(256, 2) void negmma_k(
    const __nv_bfloat16* __restrict__ A, const __nv_bfloat16* __restrict__ B,
    float* __restrict__ out, int n, int nJT) {
    __shared__ __nv_bfloat16 sA[128 * 64];
    __shared__ __nv_bfloat16 sB[128 * 64];
    int tid = threadIdx.x;
    int lane = tid & 31, warp = tid >> 5;
    int wi = warp >> 1, wj = warp & 1;
    int i0 = blockIdx.x * 128;

    uint32_t sAu = (uint32_t)__cvta_generic_to_shared(sA);
    uint32_t sBu = (uint32_t)__cvta_generic_to_shared(sB);

    int a_row = (lane & 15);
    int a_chsel = (lane >> 4);
    int b_row = (lane & 7) + ((lane >> 4) & 1) * 8;
    int b_chsel = ((lane >> 3) & 1);

    float rs[2][2] = {{0.f, 0.f}, {0.f, 0.f}};

    for (int jt = blockIdx.y; jt < nJT; jt += gridDim.y) {
        int j0 = jt * 128;
        float acc[2][8][4];
#pragma unroll
        for (int x = 0; x < 2; x++)
#pragma unroll
            for (int y = 0; y < 8; y++)
#pragma unroll
                for (int v = 0; v < 4; v++) acc[x][y][v] = 0.f;

        for (int k0 = 0; k0 < D; k0 += 64) {
#pragma unroll
            for (int t = 0; t < 4; t++) {
                int c = tid + t * 256;
                int row = c >> 3, ch = c & 7;
                uint32_t off = (uint32_t)(row * 128 + ((ch ^ (row & 7)) << 4));
                uint4 va = *(const uint4*)(A + (size_t)(i0 + row) * D + k0 + ch * 8);
                *(uint4*)((char*)sA + off) = va;
                uint4 vb = *(const uint4*)(B + (size_t)(j0 + row) * D + k0 + ch * 8);
                *(uint4*)((char*)sB + off) = vb;
            }
            __syncthreads();
#pragma unroll
            for (int ks = 0; ks < 4; ks++) {
                uint32_t afr[2][4];
#pragma unroll
                for (int mt = 0; mt < 2; mt++) {
                    int row = wi * 32 + mt * 16 + a_row;
                    int ch = ks * 2 + a_chsel;
                    uint32_t addr = sAu + (uint32_t)(row * 128 + ((ch ^ (row & 7)) << 4));
                    ldsm4(addr, afr[mt][0], afr[mt][1], afr[mt][2], afr[mt][3]);
                }
#pragma unroll
                for (int p = 0; p < 4; p++) {
                    int nrow = wj * 64 + p * 16 + b_row;
                    int ch = ks * 2 + b_chsel;
                    uint32_t addr = sBu + (uint32_t)(nrow * 128 + ((ch ^ (nrow & 7)) << 4));
                    uint32_t bf0, bf1, bf2, bf3;
                    ldsm4(addr, bf0, bf1, bf2, bf3);
#pragma unroll
                    for (int mt = 0; mt < 2; mt++) {
                        mma16816(acc[mt][2 * p], afr[mt], bf0, bf1);
                        mma16816(acc[mt][2 * p + 1], afr[mt], bf2, bf3);
                    }
                }
            }
            __syncthreads();
        }
#pragma unroll
        for (int mt = 0; mt < 2; mt++) {
#pragma unroll
            for (int nt = 0; nt < 8; nt++) {
                int j = j0 + wj * 64 + nt * 8 + (lane & 3) * 2;
                float e0 = (j < n) ? __expf(acc[mt][nt][0] * TEMP_INV) : 0.f;
                float e1 = (j + 1 < n) ? __expf(acc[mt][nt][1] * TEMP_INV) : 0.f;
                float e2 = (j < n) ? __expf(acc[mt][nt][2] * TEMP_INV) : 0.f;
                float e3 = (j + 1 < n) ? __expf(acc[mt][nt][3] * TEMP_INV) : 0.f;
                rs[mt][0] += e0 + e1;
                rs[mt][1] += e2 + e3;
            }
        }
    }
#pragma unroll
    for (int mt = 0; mt < 2; mt++) {
#pragma unroll
        for (int h = 0; h < 2; h++) {
            float v = rs[mt][h];
            v += __shfl_xor_sync(0xffffffffu, v, 1);
            v += __shfl_xor_sync(0xffffffffu, v, 2);
            if ((lane & 3) == 0) {
                int i = i0 + wi * 32 + mt * 16 + h * 8 + (lane >> 2);
                if (i < n) atomicAdd(&out[i], v);
            }
        }
    }
}

__global__ void mneg_k(const float* __restrict__ s1, const float* __restrict__ s2,
                       const int* __restrict__ src, const int* __restrict__ dst,
                       float* neg, int e) {
    int i = blockIdx.x * blockDim.x + threadIdx.x;
    if (i < e) {
        float m = logf(s1[dst[i]] + LAM * s2[src[i]]);
        atomicAdd(&neg[dst[i]], m);
    }
}

__global__ void loss_k(const float* __restrict__ pos, const float* __restrict__ neg,
                       const float* __restrict__ din, float* out, int n) {
    __shared__ float sm[256];
    float s = 0.f;
    for (int i = blockIdx.x * blockDim.x + threadIdx.x; i < n; i += gridDim.x * blockDim.x)
        s += (neg[i] - pos[i]) / din[i];
    sm[threadIdx.x] = s;
    __syncthreads();
    for (int o = 128; o > 0; o >>= 1) {
        if (threadIdx.x < o) sm[threadIdx.x] += sm[threadIdx.x + o];
        __syncthreads();
    }
    if (threadIdx.x == 0) atomicAdd(out, sm[0] / n);
}

// ------------------------------ launcher ------------------------------
static float* symf(const void* s) {
    void* p = nullptr;
    cudaGetSymbolAddress(&p, s);
    return (float*)p;
}
static __nv_bfloat16* symh(const void* s) {
    void* p = nullptr;
    cudaGetSymbolAddress(&p, s);
    return (__nv_bfloat16*)p;
}

extern "C" void kernel_launch(void* const* d_in, const int* in_sizes, int n_in,
                              void* d_out, int out_size) {
    const float* feat  = (const float*)d_in[0];
    const float* W1    = (const float*)d_in[1];
    const float* b1    = (const float*)d_in[2];
    const float* W2    = (const float*)d_in[3];
    const float* b2    = (const float*)d_in[4];
    const float* Wt1   = (const float*)d_in[5];
    const float* bt1   = (const float*)d_in[6];
    const float* gamma = (const float*)d_in[7];
    const float* beta  = (const float*)d_in[8];
    const float* Wt2   = (const float*)d_in[9];
    const float* bt2   = (const float*)d_in[10];
    const float* Wp    = (const float*)d_in[11];
    const float* bp    = (const float*)d_in[12];
    const int*   src   = (const int*)d_in[13];
    const int*   dst   = (const int*)d_in[14];

    const int IN = 512;
    int n = in_sizes[0] / IN;
    int e = in_sizes[13];
    int nTI = (n + 127) / 128;
    int npad = nTI * 128;

    float* bufA = symf(g_bufA);
    float* bufB = symf(g_bufB);
    float* tbuf = symf(g_t);
    float* hbuf = symf(g_h);
    float* zbuf = symf(g_z);
    float* qbuf = symf(g_q);
    __nv_bfloat16* featb = symh(g_featb);
    __nv_bfloat16* h1b = symh(g_h1b);
    __nv_bfloat16* tb = symh(g_tb);
    __nv_bfloat16* transb = symh(g_transb);
    __nv_bfloat16* zh = symh(g_zh);
    __nv_bfloat16* qh = symh(g_qh);
    __nv_bfloat16* W1b = symh(g_W1b);
    __nv_bfloat16* W2b = symh(g_W2b);
    __nv_bfloat16* Wt1b = symh(g_Wt1b);
    __nv_bfloat16* Wt2b = symh(g_Wt2b);
    __nv_bfloat16* Wpb = symh(g_Wpb);
    float* dout = symf(g_degout);
    float* din  = symf(g_degin);
    float* musum = symf(g_musum);
    float* varsum = symf(g_varsum);
    float* s1 = symf(g_s1);
    float* s2 = symf(g_s2);
    float* pos = symf(g_pos);
    float* neg = symf(g_neg);
    float* out = (float*)d_out;

    int nd = n * D;
    int ndpad = npad * D;
    dim3 gemm_grid(nTI, 2);
    int edge_warp_blocks = (e * 32 + 255) / 256;
    int tail = ndpad - nd;

    // conversions
    f2b_k<<<(npad * IN + 255) / 256, 256>>>(feat, featb, n * IN, npad * IN);
    wconv_k<<<(IN * D + 255) / 256, 256>>>(W1, W1b, IN, D);
    wconv_k<<<(D * D + 255) / 256, 256>>>(W2, W2b, D, D);
    wconv_k<<<(IN * D + 255) / 256, 256>>>(Wt1, Wt1b, IN, D);
    wconv_k<<<(D * D + 255) / 256, 256>>>(Wt2, Wt2b, D, D);
    wconv_k<<<(D * D + 255) / 256, 256>>>(Wp, Wpb, D, D);

    // degrees
    zero_k<<<(n + 255) / 256, 256>>>(dout, n);
    zero_k<<<(n + 255) / 256, 256>>>(din, n);
    degree_k<<<(e + 255) / 256, 256>>>(src, dst, dout, din, e);

    // GCN layer 1: xw1 = feat@W1 ; agg ; +b1 relu -> h1b (bf16)
    gemm_bf16_k<<<gemm_grid, 256>>>(featb, W1b, nullptr, bufA, nullptr, n, IN, 0);
    zero_k<<<(nd + 255) / 256, 256>>>(bufB, nd);
    scatter_k<<<edge_warp_blocks, 256>>>(bufA, src, dst, dout, din, bufB, e);
    biasact_k<<<(nd + 255) / 256, 256>>>(bufB, b1, h1b, n, 1);
    zerohtail_k<<<(tail + 255) / 256, 256>>>(h1b, nd, ndpad);

    // GCN layer 2: xw2 = h1@W2 ; agg ; +b2 -> hbuf fp32
    gemm_bf16_k<<<gemm_grid, 256>>>(h1b, W2b, nullptr, bufA, nullptr, n, D, 0);
    zero_k<<<(nd + 255) / 256, 256>>>(hbuf, nd);
    scatter_k<<<edge_warp_blocks, 256>>>(bufA, src, dst, dout, din, hbuf, e);
    biasact_k<<<(nd + 255) / 256, 256>>>(hbuf, b2, nullptr, n, 0);

    // target MLP: t = feat@Wt1+bt1 ; BN+relu -> tb ; trans = tb@Wt2+bt2 -> transb ; p = transb@Wp+bp
    gemm_bf16_k<<<gemm_grid, 256>>>(featb, Wt1b, bt1, tbuf, nullptr, n, IN, 0);
    zero_k<<<1, 256>>>(musum, D);
    zero_k<<<1, 256>>>(varsum, D);
    bnstat_k<<<100, 256>>>(tbuf, musum, varsum, n);
    bnapply_k<<<(nd + 255) / 256, 256>>>(tbuf, musum, varsum, gamma, beta, tb, n);
    zerohtail_k<<<(tail + 255) / 256, 256>>>(tb, nd, ndpad);
    gemm_bf16_k<<<gemm_grid, 256>>>(tb, Wt2b, bt2, nullptr, transb, n, D, 0);
    zerohtail_k<<<(tail + 255) / 256, 256>>>(transb, nd, ndpad);
    gemm_bf16_k<<<gemm_grid, 256>>>(transb, Wpb, bp, bufB, nullptr, n, D, 0);

    // normalize (+ bf16 copies, zero-padded rows)
    norml_k<<<(npad * 32 + 255) / 256, 256>>>(hbuf, zbuf, zh, n, npad);
    norml_k<<<(npad * 32 + 255) / 256, 256>>>(bufB, qbuf, qh, n, npad);

    // pos
    zero_k<<<(n + 255) / 256, 256>>>(pos, n);
    pos_k<<<edge_warp_blocks, 256>>>(zbuf, qbuf, src, dst, pos, e);

    // neg row sums on tensor cores
    zero_k<<<(n + 255) / 256, 256>>>(s1, n);
    zero_k<<<(n + 255) / 256, 256>>>(s2, n);
    dim3 neg_grid(nTI, 8);
    negmma_k<<<neg_grid, 256>>>(zh, zh, s1, n, nTI);
    negmma_k<<<neg_grid, 256>>>(zh, qh, s2, n, nTI);

    // m_e scatter + loss
    zero_k<<<(n + 255) / 256, 256>>>(neg, n);
    mneg_k<<<(e + 255) / 256, 256>>>(s1, s2, src, dst, neg, e);
    zero_k<<<1, 32>>>(out, out_size);
    loss_k<<<40, 256>>>(pos, neg, din, out, n);
}

// round 5
// speedup vs baseline: 12.1929x; 1.3540x over previous
#include <cuda_runtime.h>
#include <cuda_bf16.h>
#include <stdint.h>
#include <math.h>

#define NMAX 10240
#define EMAX 340000
#define D 256
#define INMAX 512
#define TEMP_INV 2.0f
#define LAM 1e-3f
#define BN_EPS 1e-5f

// ------------------------------ scratch ------------------------------
__device__ __align__(16) float g_t[NMAX * D];      // t (BN path, fp32)
__device__ __align__(16) float g_h[NMAX * D];      // GCN output h (fp32)
__device__ __align__(16) float g_p[NMAX * D];      // projector out (fp32)
__device__ __align__(16) float g_z[NMAX * D];
__device__ __align__(16) float g_q[NMAX * D];
__device__ __align__(16) __nv_bfloat16 g_featb[NMAX * INMAX];
__device__ __align__(16) __nv_bfloat16 g_xwb[NMAX * D];
__device__ __align__(16) __nv_bfloat16 g_h1b[NMAX * D];
__device__ __align__(16) __nv_bfloat16 g_tb[NMAX * D];
__device__ __align__(16) __nv_bfloat16 g_transb[NMAX * D];
__device__ __align__(16) __nv_bfloat16 g_zh[NMAX * D];
__device__ __align__(16) __nv_bfloat16 g_qh[NMAX * D];
__device__ __align__(16) __nv_bfloat16 g_W1b[INMAX * D];   // [N,K]
__device__ __align__(16) __nv_bfloat16 g_W2b[D * D];
__device__ __align__(16) __nv_bfloat16 g_Wt1b[INMAX * D];
__device__ __align__(16) __nv_bfloat16 g_Wt2b[D * D];
__device__ __align__(16) __nv_bfloat16 g_Wpb[D * D];
__device__ float g_degout[NMAX];
__device__ float g_degin[NMAX];
__device__ float g_rsd[NMAX];
__device__ int   g_cnt[NMAX];
__device__ int   g_off[NMAX + 1];
__device__ int   g_cur[NMAX];
__device__ int   g_csrc[EMAX];
__device__ float g_musum[D];
__device__ float g_varsum[D];
__device__ float g_s1[NMAX];
__device__ float g_s2[NMAX];
__device__ float g_pos[NMAX];
__device__ float g_neg[NMAX];

// ------------------------------ small kernels ------------------------------
__global__ void zero_k(float* p, int n) {
    int i = blockIdx.x * blockDim.x + threadIdx.x;
    if (i < n) p[i] = 0.f;
}
__global__ void zeroi_k(int* p, int n) {
    int i = blockIdx.x * blockDim.x + threadIdx.x;
    if (i < n) p[i] = 0;
}

__global__ void f2b_k(const float* __restrict__ x, __nv_bfloat16* __restrict__ y,
                      int n, int ntot) {
    int i = blockIdx.x * blockDim.x + threadIdx.x;
    if (i < ntot) y[i] = __float2bfloat16(i < n ? x[i] : 0.f);
}

// W[K,N] row-major -> Wt[N,K] bf16
__global__ void wconv_k(const float* __restrict__ W, __nv_bfloat16* __restrict__ Wt,
                        int K, int N) {
    int i = blockIdx.x * blockDim.x + threadIdx.x;
    if (i < K * N) {
        int k = i / N, n = i % N;
        Wt[n * K + k] = __float2bfloat16(W[i]);
    }
}

__global__ void zerohtail_k(__nv_bfloat16* p, int from, int to) {
    int i = from + blockIdx.x * blockDim.x + threadIdx.x;
    if (i < to) p[i] = __float2bfloat16(0.f);
}

__global__ void degree_k(const int* __restrict__ src, const int* __restrict__ dst,
                         float* dout, float* din, int* cnt, int e) {
    int i = blockIdx.x * blockDim.x + threadIdx.x;
    if (i < e) {
        atomicAdd(&dout[src[i]], 1.f);
        atomicAdd(&din[dst[i]], 1.f);
        atomicAdd(&cnt[dst[i]], 1);
    }
}

__global__ void rsd_k(const float* __restrict__ dout, float* rsd, int n) {
    int i = blockIdx.x * blockDim.x + threadIdx.x;
    if (i < n) rsd[i] = rsqrtf(dout[i]);
}

// single-block exclusive scan, n <= 1024*L
__global__ void scan_k(const int* __restrict__ cnt, int* off, int n) {
    __shared__ int ts[1024];
    int t = threadIdx.x;
    int L = (n + 1023) >> 10;
    int b = t * L, eidx = min(b + L, n);
    int s = 0;
    for (int i = b; i < eidx; i++) s += cnt[i];
    ts[t] = s;
    __syncthreads();
    for (int d2 = 1; d2 < 1024; d2 <<= 1) {
        int v = (t >= d2) ? ts[t - d2] : 0;
        __syncthreads();
        ts[t] += v;
        __syncthreads();
    }
    int base = (t == 0) ? 0 : ts[t - 1];
    for (int i = b; i < eidx; i++) { off[i] = base; base += cnt[i]; }
    if (t == 1023) off[n] = ts[1023];
}

__global__ void fillcsr_k(const int* __restrict__ src, const int* __restrict__ dst,
                          const int* __restrict__ off, int* cur, int* csrc, int e) {
    int i = blockIdx.x * blockDim.x + threadIdx.x;
    if (i < e) {
        int d = dst[i];
        int p = off[d] + atomicAdd(&cur[d], 1);
        csrc[p] = src[i];
    }
}

// gather aggregation: out[d] = rsqrt(din[d]) * sum_p xw[src_p]*rsqrt(dout[src_p]) + bias
// one warp per dst node, bf16 input, fp32 accum, fused bias/relu, fp32/bf16 outputs
__global__ void gather_agg_k(const __nv_bfloat16* __restrict__ xw,
                             const int* __restrict__ csrc, const int* __restrict__ off,
                             const float* __restrict__ rsd, const float* __restrict__ din,
                             const float* __restrict__ bias,
                             float* outf, __nv_bfloat16* outh, int n, int relu) {
    int d = (blockIdx.x * blockDim.x + threadIdx.x) >> 5;
    int lane = threadIdx.x & 31;
    if (d >= n) return;
    float acc[8] = {};
    int p0 = off[d], p1 = off[d + 1];
    for (int p = p0; p < p1; p++) {
        int s = csrc[p];
        float w = rsd[s];
        uint4 v = *((const uint4*)(xw + (size_t)s * D) + lane);
        const __nv_bfloat16* hv = (const __nv_bfloat16*)&v;
#pragma unroll
        for (int k = 0; k < 8; k++) acc[k] += __bfloat162float(hv[k]) * w;
    }
    float sc = rsqrtf(din[d]);
    int col = lane * 8;
    float o[8];
#pragma unroll
    for (int k = 0; k < 8; k++) {
        float v = acc[k] * sc + bias[col + k];
        o[k] = relu ? fmaxf(v, 0.f) : v;
    }
    if (outf) {
        float4* fr = (float4*)(outf + (size_t)d * D + col);
        fr[0] = make_float4(o[0], o[1], o[2], o[3]);
        fr[1] = make_float4(o[4], o[5], o[6], o[7]);
    }
    if (outh) {
        __nv_bfloat16 hb[8];
#pragma unroll
        for (int k = 0; k < 8; k++) hb[k] = __float2bfloat16(o[k]);
        *(uint4*)(outh + (size_t)d * D + col) = *(uint4*)hb;
    }
}

__global__ void bnstat_k(const float* __restrict__ t, float* musum, float* varsum, int M) {
    int col = threadIdx.x;
    int rpb = (M + gridDim.x - 1) / gridDim.x;
    int r0 = blockIdx.x * rpb;
    int r1 = min(r0 + rpb, M);
    float s = 0.f, s2 = 0.f;
    for (int r = r0; r < r1; r++) {
        float v = t[(size_t)r * D + col];
        s += v; s2 += v * v;
    }
    atomicAdd(&musum[col], s);
    atomicAdd(&varsum[col], s2);
}

__global__ void bnapply_k(const float* __restrict__ t, const float* __restrict__ musum,
                          const float* __restrict__ varsum,
                          const float* __restrict__ gamma, const float* __restrict__ beta,
                          __nv_bfloat16* th, int M) {
    int i = blockIdx.x * blockDim.x + threadIdx.x;
    if (i < M * D) {
        int c = i & (D - 1);
        float mu = musum[c] / M;
        float var = varsum[c] / M - mu * mu;
        float v = (t[i] - mu) * rsqrtf(var + BN_EPS) * gamma[c] + beta[c];
        th[i] = __float2bfloat16(fmaxf(v, 0.f));
    }
}

__global__ void norml_k(const float* __restrict__ x, float* __restrict__ z,
                        __nv_bfloat16* __restrict__ zh, int M, int Mpad) {
    int row = (blockIdx.x * blockDim.x + threadIdx.x) >> 5;
    int lane = threadIdx.x & 31;
    if (row >= Mpad) return;
    __nv_bfloat16* hr = zh + (size_t)row * D;
    if (row >= M) {
#pragma unroll
        for (int c = 0; c < D / 32; c++) hr[lane + 32 * c] = __float2bfloat16(0.f);
        return;
    }
    const float* xr = x + (size_t)row * D;
    float s = 0.f;
#pragma unroll
    for (int c = 0; c < D / 32; c++) {
        float v = xr[lane + 32 * c];
        s += v * v;
    }
#pragma unroll
    for (int o = 16; o > 0; o >>= 1) s += __shfl_xor_sync(0xffffffffu, s, o);
    float inv = 1.f / fmaxf(sqrtf(s), 1e-12f);
    float* zr = z + (size_t)row * D;
#pragma unroll
    for (int c = 0; c < D / 32; c++) {
        int f = lane + 32 * c;
        float v = xr[f] * inv;
        zr[f] = v;
        hr[f] = __float2bfloat16(v);
    }
}

// pos gather: pos[d] = TEMP_INV * dot(q[d], sum_p z[src_p]); one warp per d
__global__ void gather_pos_k(const __nv_bfloat16* __restrict__ zh,
                             const float* __restrict__ q,
                             const int* __restrict__ csrc, const int* __restrict__ off,
                             float* pos, int n) {
    int d = (blockIdx.x * blockDim.x + threadIdx.x) >> 5;
    int lane = threadIdx.x & 31;
    if (d >= n) return;
    int col = lane * 8;
    const float4* qr = (const float4*)(q + (size_t)d * D + col);
    float4 qa = qr[0], qb = qr[1];
    float sz[8] = {};
    int p0 = off[d], p1 = off[d + 1];
    for (int p = p0; p < p1; p++) {
        int s = csrc[p];
        uint4 v = *((const uint4*)(zh + (size_t)s * D) + lane);
        const __nv_bfloat16* hv = (const __nv_bfloat16*)&v;
#pragma unroll
        for (int k = 0; k < 8; k++) sz[k] += __bfloat162float(hv[k]);
    }
    float dot = sz[0] * qa.x + sz[1] * qa.y + sz[2] * qa.z + sz[3] * qa.w +
                sz[4] * qb.x + sz[5] * qb.y + sz[6] * qb.z + sz[7] * qb.w;
#pragma unroll
    for (int o = 16; o > 0; o >>= 1) dot += __shfl_xor_sync(0xffffffffu, dot, o);
    if (lane == 0) pos[d] = dot * TEMP_INV;
}

// mneg gather: neg[d] = sum_p log(s1[d] + LAM*s2[src_p]); one warp per d
__global__ void gather_mneg_k(const float* __restrict__ s1, const float* __restrict__ s2,
                              const int* __restrict__ csrc, const int* __restrict__ off,
                              float* neg, int n) {
    int d = (blockIdx.x * blockDim.x + threadIdx.x) >> 5;
    int lane = threadIdx.x & 31;
    if (d >= n) return;
    float base = s1[d];
    float acc = 0.f;
    int p0 = off[d], p1 = off[d + 1];
    for (int p = p0 + lane; p < p1; p += 32)
        acc += __logf(base + LAM * s2[csrc[p]]);
#pragma unroll
    for (int o = 16; o > 0; o >>= 1) acc += __shfl_xor_sync(0xffffffffu, acc, o);
    if (lane == 0) neg[d] = acc;
}

// ---------------- mma helpers ----------------
__device__ __forceinline__ void ldsm4(uint32_t addr, uint32_t& r0, uint32_t& r1,
                                      uint32_t& r2, uint32_t& r3) {
    asm volatile("ldmatrix.sync.aligned.m8n8.x4.shared.b16 {%0,%1,%2,%3}, [%4];"
                 : "=r"(r0), "=r"(r1), "=r"(r2), "=r"(r3) : "r"(addr));
}

__device__ __forceinline__ void mma16816(float* c, const uint32_t* a,
                                         uint32_t b0, uint32_t b1) {
    asm volatile(
        "mma.sync.aligned.m16n8k16.row.col.f32.bf16.bf16.f32 "
        "{%0,%1,%2,%3}, {%4,%5,%6,%7}, {%8,%9}, {%0,%1,%2,%3};"
        : "+f"(c[0]), "+f"(c[1]), "+f"(c[2]), "+f"(c[3])
        : "r"(a[0]), "r"(a[1]), "r"(a[2]), "r"(a[3]), "r"(b0), "r"(b1));
}

__device__ __forceinline__ void cp16(uint32_t saddr, const void* g) {
    asm volatile("cp.async.cg.shared.global [%0], [%1], 16;"
                 :: "r"(saddr), "l"(g) : "memory");
}

// load one 128x64 bf16 tile pair (A, B) into smem stage via cp.async
__device__ __forceinline__ void load_tiles64(uint32_t sA, uint32_t sB,
        const __nv_bfloat16* Ag, const __nv_bfloat16* Bg, int k0,
        int lda, int ldb, int tid) {
#pragma unroll
    for (int t = 0; t < 4; t++) {
        int c = tid + t * 256;           // 0..1023 16B chunks
        int row = c >> 3, ch = c & 7;
        uint32_t off = (uint32_t)(row * 128 + ((ch ^ (row & 7)) << 4));
        cp16(sA + off, Ag + (size_t)row * lda + k0 + ch * 8);
        cp16(sB + off, Bg + (size_t)row * ldb + k0 + ch * 8);
    }
    asm volatile("cp.async.commit_group;" ::: "memory");
}

#define STAGE_BYTES 32768

// ---------------- bf16 tensor GEMM (pipelined): C = A[Mpad,K] @ Wt[256,K]^T ----------------
__global__ __launch_bounds__(256, 2) void gemm_bf16_k(
    const __nv_bfloat16* __restrict__ A, const __nv_bfloat16* __restrict__ Wt,
    const float* __restrict__ bias, float* __restrict__ Cf,
    __nv_bfloat16* __restrict__ Ch, int M, int K, int relu) {
    extern __shared__ char dsm[];
    uint32_t sbase = (uint32_t)__cvta_generic_to_shared(dsm);
    int tid = threadIdx.x;
    int lane = tid & 31, warp = tid >> 5;
    int wi = warp >> 1, wj = warp & 1;
    int i0 = blockIdx.x * 128, j0 = blockIdx.y * 128;

    int a_row = (lane & 15);
    int a_chsel = (lane >> 4);
    int b_row = (lane & 7) + ((lane >> 4) & 1) * 8;
    int b_chsel = ((lane >> 3) & 1);

    const __nv_bfloat16* Ag = A + (size_t)i0 * K;
    const __nv_bfloat16* Bg = Wt + (size_t)j0 * K;

    float acc[2][8][4];
#pragma unroll
    for (int x = 0; x < 2; x++)
#pragma unroll
        for (int y = 0; y < 8; y++)
#pragma unroll
            for (int v = 0; v < 4; v++) acc[x][y][v] = 0.f;

    int KT = K >> 6;
    load_tiles64(sbase, sbase + 16384, Ag, Bg, 0, K, K, tid);
    for (int kt = 0; kt < KT; kt++) {
        asm volatile("cp.async.wait_group 0;" ::: "memory");
        __syncthreads();
        if (kt + 1 < KT) {
            uint32_t sa = sbase + ((kt + 1) & 1) * STAGE_BYTES;
            load_tiles64(sa, sa + 16384, Ag, Bg, (kt + 1) * 64, K, K, tid);
        }
        uint32_t sAu = sbase + (kt & 1) * STAGE_BYTES;
        uint32_t sBu = sAu + 16384;
#pragma unroll
        for (int ks = 0; ks < 4; ks++) {
            uint32_t afr[2][4];
#pragma unroll
            for (int mt = 0; mt < 2; mt++) {
                int row = wi * 32 + mt * 16 + a_row;
                int ch = ks * 2 + a_chsel;
                uint32_t addr = sAu + (uint32_t)(row * 128 + ((ch ^ (row & 7)) << 4));
                ldsm4(addr, afr[mt][0], afr[mt][1], afr[mt][2], afr[mt][3]);
            }
#pragma unroll
            for (int p = 0; p < 4; p++) {
                int nrow = wj * 64 + p * 16 + b_row;
                int ch = ks * 2 + b_chsel;
                uint32_t addr = sBu + (uint32_t)(nrow * 128 + ((ch ^ (nrow & 7)) << 4));
                uint32_t bf0, bf1, bf2, bf3;
                ldsm4(addr, bf0, bf1, bf2, bf3);
#pragma unroll
                for (int mt = 0; mt < 2; mt++) {
                    mma16816(acc[mt][2 * p], afr[mt], bf0, bf1);
                    mma16816(acc[mt][2 * p + 1], afr[mt], bf2, bf3);
                }
            }
        }
    }
    // epilogue
#pragma unroll
    for (int mt = 0; mt < 2; mt++) {
        int r0 = i0 + wi * 32 + mt * 16 + (lane >> 2);
#pragma unroll
        for (int nt = 0; nt < 8; nt++) {
            int col = j0 + wj * 64 + nt * 8 + (lane & 3) * 2;
            float b0 = bias ? bias[col] : 0.f;
            float b1 = bias ? bias[col + 1] : 0.f;
            float v0 = acc[mt][nt][0] + b0, v1 = acc[mt][nt][1] + b1;
            float v2 = acc[mt][nt][2] + b0, v3 = acc[mt][nt][3] + b1;
            if (relu) {
                v0 = fmaxf(v0, 0.f); v1 = fmaxf(v1, 0.f);
                v2 = fmaxf(v2, 0.f); v3 = fmaxf(v3, 0.f);
            }
            if (r0 < M) {
                if (Cf) { Cf[(size_t)r0 * D + col] = v0; Cf[(size_t)r0 * D + col + 1] = v1; }
                if (Ch) {
                    Ch[(size_t)r0 * D + col] = __float2bfloat16(v0);
                    Ch[(size_t)r0 * D + col + 1] = __float2bfloat16(v1);
                }
            }
            int r1 = r0 + 8;
            if (r1 < M) {
                if (Cf) { Cf[(size_t)r1 * D + col] = v2; Cf[(size_t)r1 * D + col + 1] = v3; }
                if (Ch) {
                    Ch[(size_t)r1 * D + col] = __float2bfloat16(v2);
                    Ch[(size_t)r1 * D + col + 1] = __float2bfloat16(v3);
                }
            }
        }
    }
}

// ---------------- bf16 fused GEMM+exp+rowsum (pipelined) ----------------
__global__ __launch_bounds__(256, 2) void negmma_k(
    const __nv_bfloat16* __restrict__ A, const __nv_bfloat16* __restrict__ B,
    float* __restrict__ out, int n, int nJT) {
    extern __shared__ char dsm[];
    uint32_t sbase = (uint32_t)__cvta_generic_to_shared(dsm);
    int tid = threadIdx.x;
    int lane = tid & 31, warp = tid >> 5;
    int wi = warp >> 1, wj = warp & 1;
    int i0 = blockIdx.x * 128;

    int a_row = (lane & 15);
    int a_chsel = (lane >> 4);
    int b_row = (lane & 7) + ((lane >> 4) & 1) * 8;
    int b_chsel = ((lane >> 3) & 1);

    const __nv_bfloat16* Ag = A + (size_t)i0 * D;
    float rs[2][2] = {{0.f, 0.f}, {0.f, 0.f}};

    for (int jt = blockIdx.y; jt < nJT; jt += gridDim.y) {
        int j0 = jt * 128;
        const __nv_bfloat16* Bg = B + (size_t)j0 * D;
        float acc[2][8][4];
#pragma unroll
        for (int x = 0; x < 2; x++)
#pragma unroll
            for (int y = 0; y < 8; y++)
#pragma unroll
                for (int v = 0; v < 4; v++) acc[x][y][v] = 0.f;

        load_tiles64(sbase, sbase + 16384, Ag, Bg, 0, D, D, tid);
#pragma unroll
        for (int kt = 0; kt < 4; kt++) {
            asm volatile("cp.async.wait_group 0;" ::: "memory");
            __syncthreads();
            if (kt < 3) {
                uint32_t sa = sbase + ((kt + 1) & 1) * STAGE_BYTES;
                load_tiles64(sa, sa + 16384, Ag, Bg, (kt + 1) * 64, D, D, tid);
            }
            uint32_t sAu = sbase + (kt & 1) * STAGE_BYTES;
            uint32_t sBu = sAu + 16384;
#pragma unroll
            for (int ks = 0; ks < 4; ks++) {
                uint32_t afr[2][4];
#pragma unroll
                for (int mt = 0; mt < 2; mt++) {
                    int row = wi * 32 + mt * 16 + a_row;
                    int ch = ks * 2 + a_chsel;
                    uint32_t addr = sAu + (uint32_t)(row * 128 + ((ch ^ (row & 7)) << 4));
                    ldsm4(addr, afr[mt][0], afr[mt][1], afr[mt][2], afr[mt][3]);
                }
#pragma unroll
                for (int p = 0; p < 4; p++) {
                    int nrow = wj * 64 + p * 16 + b_row;
                    int ch = ks * 2 + b_chsel;
                    uint32_t addr = sBu + (uint32_t)(nrow * 128 + ((ch ^ (nrow & 7)) << 4));
                    uint32_t bf0, bf1, bf2, bf3;
                    ldsm4(addr, bf0, bf1, bf2, bf3);
#pragma unroll
                    for (int mt = 0; mt < 2; mt++) {
                        mma16816(acc[mt][2 * p], afr[mt], bf0, bf1);
                        mma16816(acc[mt][2 * p + 1], afr[mt], bf2, bf3);
                    }
                }
            }
            __syncthreads();
        }
#pragma unroll
        for (int mt = 0; mt < 2; mt++) {
#pragma unroll
            for (int nt = 0; nt < 8; nt++) {
                int j = j0 + wj * 64 + nt * 8 + (lane & 3) * 2;
                float e0 = (j < n) ? __expf(acc[mt][nt][0] * TEMP_INV) : 0.f;
                float e1 = (j + 1 < n) ? __expf(acc[mt][nt][1] * TEMP_INV) : 0.f;
                float e2 = (j < n) ? __expf(acc[mt][nt][2] * TEMP_INV) : 0.f;
                float e3 = (j + 1 < n) ? __expf(acc[mt][nt][3] * TEMP_INV) : 0.f;
                rs[mt][0] += e0 + e1;
                rs[mt][1] += e2 + e3;
            }
        }
    }
#pragma unroll
    for (int mt = 0; mt < 2; mt++) {
#pragma unroll
        for (int h = 0; h < 2; h++) {
            float v = rs[mt][h];
            v += __shfl_xor_sync(0xffffffffu, v, 1);
            v += __shfl_xor_sync(0xffffffffu, v, 2);
            if ((lane & 3) == 0) {
                int i = i0 + wi * 32 + mt * 16 + h * 8 + (lane >> 2);
                if (i < n) atomicAdd(&out[i], v);
            }
        }
    }
}

__global__ void loss_k(const float* __restrict__ pos, const float* __restrict__ neg,
                       const float* __restrict__ din, float* out, int n) {
    __shared__ float sm[256];
    float s = 0.f;
    for (int i = blockIdx.x * blockDim.x + threadIdx.x; i < n; i += gridDim.x * blockDim.x)
        s += (neg[i] - pos[i]) / din[i];
    sm[threadIdx.x] = s;
    __syncthreads();
    for (int o = 128; o > 0; o >>= 1) {
        if (threadIdx.x < o) sm[threadIdx.x] += sm[threadIdx.x + o];
        __syncthreads();
    }
    if (threadIdx.x == 0) atomicAdd(out, sm[0] / n);
}

// ------------------------------ launcher ------------------------------
static float* symf(const void* s) { void* p = nullptr; cudaGetSymbolAddress(&p, s); return (float*)p; }
static int* symi(const void* s) { void* p = nullptr; cudaGetSymbolAddress(&p, s); return (int*)p; }
static __nv_bfloat16* symh(const void* s) { void* p = nullptr; cudaGetSymbolAddress(&p, s); return (__nv_bfloat16*)p; }

extern "C" void kernel_launch(void* const* d_in, const int* in_sizes, int n_in,
                              void* d_out, int out_size) {
    const float* feat  = (const float*)d_in[0];
    const float* W1    = (const float*)d_in[1];
    const float* b1    = (const float*)d_in[2];
    const float* W2    = (const float*)d_in[3];
    const float* b2    = (const float*)d_in[4];
    const float* Wt1   = (const float*)d_in[5];
    const float* bt1   = (const float*)d_in[6];
    const float* gamma = (const float*)d_in[7];
    const float* beta  = (const float*)d_in[8];
    const float* Wt2   = (const float*)d_in[9];
    const float* bt2   = (const float*)d_in[10];
    const float* Wp    = (const float*)d_in[11];
    const float* bp    = (const float*)d_in[12];
    const int*   src   = (const int*)d_in[13];
    const int*   dst   = (const int*)d_in[14];

    const int IN = 512;
    int n = in_sizes[0] / IN;
    int e = in_sizes[13];
    int nTI = (n + 127) / 128;
    int npad = nTI * 128;

    float* tbuf = symf(g_t);
    float* hbuf = symf(g_h);
    float* pbuf = symf(g_p);
    float* zbuf = symf(g_z);
    float* qbuf = symf(g_q);
    __nv_bfloat16* featb = symh(g_featb);
    __nv_bfloat16* xwb = symh(g_xwb);
    __nv_bfloat16* h1b = symh(g_h1b);
    __nv_bfloat16* tb = symh(g_tb);
    __nv_bfloat16* transb = symh(g_transb);
    __nv_bfloat16* zh = symh(g_zh);
    __nv_bfloat16* qh = symh(g_qh);
    __nv_bfloat16* W1b = symh(g_W1b);
    __nv_bfloat16* W2b = symh(g_W2b);
    __nv_bfloat16* Wt1b = symh(g_Wt1b);
    __nv_bfloat16* Wt2b = symh(g_Wt2b);
    __nv_bfloat16* Wpb = symh(g_Wpb);
    float* dout = symf(g_degout);
    float* din  = symf(g_degin);
    float* rsd  = symf(g_rsd);
    int* cnt = symi(g_cnt);
    int* off = symi(g_off);
    int* cur = symi(g_cur);
    int* csrc = symi(g_csrc);
    float* musum = symf(g_musum);
    float* varsum = symf(g_varsum);
    float* s1 = symf(g_s1);
    float* s2 = symf(g_s2);
    float* pos = symf(g_pos);
    float* neg = symf(g_neg);
    float* out = (float*)d_out;

    int nd = n * D;
    int ndpad = npad * D;
    int tail = ndpad - nd;
    dim3 gemm_grid(nTI, 2);
    int node_warp_blocks = (n * 32 + 255) / 256;

    cudaFuncSetAttribute(gemm_bf16_k, cudaFuncAttributeMaxDynamicSharedMemorySize, 2 * STAGE_BYTES);
    cudaFuncSetAttribute(negmma_k, cudaFuncAttributeMaxDynamicSharedMemorySize, 2 * STAGE_BYTES);

    // conversions
    f2b_k<<<(npad * IN + 255) / 256, 256>>>(feat, featb, n * IN, npad * IN);
    wconv_k<<<(IN * D + 255) / 256, 256>>>(W1, W1b, IN, D);
    wconv_k<<<(D * D + 255) / 256, 256>>>(W2, W2b, D, D);
    wconv_k<<<(IN * D + 255) / 256, 256>>>(Wt1, Wt1b, IN, D);
    wconv_k<<<(D * D + 255) / 256, 256>>>(Wt2, Wt2b, D, D);
    wconv_k<<<(D * D + 255) / 256, 256>>>(Wp, Wpb, D, D);

    // degrees + CSR by dst
    zero_k<<<(n + 255) / 256, 256>>>(dout, n);
    zero_k<<<(n + 255) / 256, 256>>>(din, n);
    zeroi_k<<<(n + 255) / 256, 256>>>(cnt, n);
    degree_k<<<(e + 255) / 256, 256>>>(src, dst, dout, din, cnt, e);
    rsd_k<<<(n + 255) / 256, 256>>>(dout, rsd, n);
    scan_k<<<1, 1024>>>(cnt, off, n);
    zeroi_k<<<(n + 255) / 256, 256>>>(cur, n);
    fillcsr_k<<<(e + 255) / 256, 256>>>(src, dst, off, cur, csrc, e);

    // GCN layer 1: xw1 = feat@W1 (bf16) ; gather+b1+relu -> h1b
    gemm_bf16_k<<<gemm_grid, 256, 2 * STAGE_BYTES>>>(featb, W1b, nullptr, nullptr, xwb, n, IN, 0);
    gather_agg_k<<<node_warp_blocks, 256>>>(xwb, csrc, off, rsd, din, b1, nullptr, h1b, n, 1);
    zerohtail_k<<<(tail + 255) / 256, 256>>>(h1b, nd, ndpad);

    // GCN layer 2: xw2 = h1@W2 ; gather+b2 -> hbuf fp32
    gemm_bf16_k<<<gemm_grid, 256, 2 * STAGE_BYTES>>>(h1b, W2b, nullptr, nullptr, xwb, n, D, 0);
    gather_agg_k<<<node_warp_blocks, 256>>>(xwb, csrc, off, rsd, din, b2, hbuf, nullptr, n, 0);

    // target MLP
    gemm_bf16_k<<<gemm_grid, 256, 2 * STAGE_BYTES>>>(featb, Wt1b, bt1, tbuf, nullptr, n, IN, 0);
    zero_k<<<1, 256>>>(musum, D);
    zero_k<<<1, 256>>>(varsum, D);
    bnstat_k<<<100, 256>>>(tbuf, musum, varsum, n);
    bnapply_k<<<(nd + 255) / 256, 256>>>(tbuf, musum, varsum, gamma, beta, tb, n);
    zerohtail_k<<<(tail + 255) / 256, 256>>>(tb, nd, ndpad);
    gemm_bf16_k<<<gemm_grid, 256, 2 * STAGE_BYTES>>>(tb, Wt2b, bt2, nullptr, transb, n, D, 0);
    zerohtail_k<<<(tail + 255) / 256, 256>>>(transb, nd, ndpad);
    gemm_bf16_k<<<gemm_grid, 256, 2 * STAGE_BYTES>>>(transb, Wpb, bp, pbuf, nullptr, n, D, 0);

    // normalize
    norml_k<<<(npad * 32 + 255) / 256, 256>>>(hbuf, zbuf, zh, n, npad);
    norml_k<<<(npad * 32 + 255) / 256, 256>>>(pbuf, qbuf, qh, n, npad);

    // pos (gather)
    gather_pos_k<<<node_warp_blocks, 256>>>(zh, qbuf, csrc, off, pos, n);

    // neg row sums (tensor cores)
    zero_k<<<(n + 255) / 256, 256>>>(s1, n);
    zero_k<<<(n + 255) / 256, 256>>>(s2, n);
    dim3 neg_grid(nTI, 8);
    negmma_k<<<neg_grid, 256, 2 * STAGE_BYTES>>>(zh, zh, s1, n, nTI);
    negmma_k<<<neg_grid, 256, 2 * STAGE_BYTES>>>(zh, qh, s2, n, nTI);

    // mneg (gather) + loss
    gather_mneg_k<<<node_warp_blocks, 256>>>(s1, s2, csrc, off, neg, n);
    zero_k<<<1, 32>>>(out, out_size);
    loss_k<<<40, 256>>>(pos, neg, din, out, n);
}

// round 6
// speedup vs baseline: 12.9534x; 1.0624x over previous
#include <cuda_runtime.h>
#include <cuda_bf16.h>
#include <stdint.h>
#include <math.h>

#define NMAX 10240
#define EMAX 340000
#define D 256
#define INMAX 512
#define TEMP_INV 2.0f
#define LAM 1e-3f
#define BN_EPS 1e-5f

// ------------------------------ scratch ------------------------------
__device__ __align__(16) float g_t[NMAX * D];
__device__ __align__(16) float g_h[NMAX * D];
__device__ __align__(16) float g_p[NMAX * D];
__device__ __align__(16) float g_z[NMAX * D];
__device__ __align__(16) float g_q[NMAX * D];
__device__ __align__(16) __nv_bfloat16 g_featb[NMAX * INMAX];
__device__ __align__(16) __nv_bfloat16 g_xwb[NMAX * D];
__device__ __align__(16) __nv_bfloat16 g_h1b[NMAX * D];
__device__ __align__(16) __nv_bfloat16 g_tb[NMAX * D];
__device__ __align__(16) __nv_bfloat16 g_transb[NMAX * D];
__device__ __align__(16) __nv_bfloat16 g_zh[NMAX * D];
__device__ __align__(16) __nv_bfloat16 g_qh[NMAX * D];
__device__ __align__(16) __nv_bfloat16 g_W1b[INMAX * D];
__device__ __align__(16) __nv_bfloat16 g_W2b[D * D];
__device__ __align__(16) __nv_bfloat16 g_Wt1b[INMAX * D];
__device__ __align__(16) __nv_bfloat16 g_Wt2b[D * D];
__device__ __align__(16) __nv_bfloat16 g_Wpb[D * D];
__device__ float g_degout[NMAX];
__device__ float g_degin[NMAX];
__device__ float g_rsd[NMAX];
__device__ int   g_cnt[NMAX];
__device__ int   g_off[NMAX + 1];
__device__ int   g_cur[NMAX];
__device__ int   g_csrc[EMAX];
__device__ float g_musum[D];
__device__ float g_varsum[D];
__device__ float g_s1[NMAX];
__device__ float g_s2[NMAX];
__device__ float g_pos[NMAX];

// ------------------------------ small kernels ------------------------------
__global__ void zero2_k(float* a, float* b, int n) {
    int i = blockIdx.x * blockDim.x + threadIdx.x;
    if (i < n) { a[i] = 0.f; b[i] = 0.f; }
}
__global__ void zero3_k(float* a, float* b, int* c, int n) {
    int i = blockIdx.x * blockDim.x + threadIdx.x;
    if (i < n) { a[i] = 0.f; b[i] = 0.f; c[i] = 0; }
}
__global__ void zero_k(float* p, int n) {
    int i = blockIdx.x * blockDim.x + threadIdx.x;
    if (i < n) p[i] = 0.f;
}

__global__ void f2b_k(const float* __restrict__ x, __nv_bfloat16* __restrict__ y,
                      int n, int ntot) {
    int i = blockIdx.x * blockDim.x + threadIdx.x;
    if (i < ntot) y[i] = __float2bfloat16(i < n ? x[i] : 0.f);
}

// all 5 weight transposes in one launch. W[K,N=256] -> Wt[N,K] bf16.
__global__ void wconvall_k(const float* W1, const float* Wt1,
                           const float* W2, const float* Wt2, const float* Wp,
                           __nv_bfloat16* W1b, __nv_bfloat16* Wt1b,
                           __nv_bfloat16* W2b, __nv_bfloat16* Wt2b,
                           __nv_bfloat16* Wpb) {
    int i = blockIdx.x * blockDim.x + threadIdx.x;
    const float* W; __nv_bfloat16* O; int K, li;
    if (i < 131072)        { W = W1;  O = W1b;  K = 512; li = i; }
    else if (i < 262144)   { W = Wt1; O = Wt1b; K = 512; li = i - 131072; }
    else if (i < 327680)   { W = W2;  O = W2b;  K = 256; li = i - 262144; }
    else if (i < 393216)   { W = Wt2; O = Wt2b; K = 256; li = i - 327680; }
    else if (i < 458752)   { W = Wp;  O = Wpb;  K = 256; li = i - 393216; }
    else return;
    int k = li >> 8, n = li & 255;
    O[n * K + k] = __float2bfloat16(W[(size_t)k * 256 + n]);
}

__global__ void zerohtail_k(__nv_bfloat16* p, int from, int to) {
    int i = from + blockIdx.x * blockDim.x + threadIdx.x;
    if (i < to) p[i] = __float2bfloat16(0.f);
}

__global__ void degree_k(const int* __restrict__ src, const int* __restrict__ dst,
                         float* dout, float* din, int* cnt, int e) {
    int i = blockIdx.x * blockDim.x + threadIdx.x;
    if (i < e) {
        atomicAdd(&dout[src[i]], 1.f);
        atomicAdd(&din[dst[i]], 1.f);
        atomicAdd(&cnt[dst[i]], 1);
    }
}

__global__ void rsdcur_k(const float* __restrict__ dout, float* rsd, int* cur, int n) {
    int i = blockIdx.x * blockDim.x + threadIdx.x;
    if (i < n) { rsd[i] = rsqrtf(dout[i]); cur[i] = 0; }
}

__global__ void scan_k(const int* __restrict__ cnt, int* off, int n) {
    __shared__ int ts[1024];
    int t = threadIdx.x;
    int L = (n + 1023) >> 10;
    int b = t * L, eidx = min(b + L, n);
    int s = 0;
    for (int i = b; i < eidx; i++) s += cnt[i];
    ts[t] = s;
    __syncthreads();
    for (int d2 = 1; d2 < 1024; d2 <<= 1) {
        int v = (t >= d2) ? ts[t - d2] : 0;
        __syncthreads();
        ts[t] += v;
        __syncthreads();
    }
    int base = (t == 0) ? 0 : ts[t - 1];
    for (int i = b; i < eidx; i++) { off[i] = base; base += cnt[i]; }
    if (t == 1023) off[n] = ts[1023];
}

__global__ void fillcsr_k(const int* __restrict__ src, const int* __restrict__ dst,
                          const int* __restrict__ off, int* cur, int* csrc, int e) {
    int i = blockIdx.x * blockDim.x + threadIdx.x;
    if (i < e) {
        int d = dst[i];
        int p = off[d] + atomicAdd(&cur[d], 1);
        csrc[p] = src[i];
    }
}

// gather agg, one warp per dst node, unroll-4 for MLP
__global__ void gather_agg_k(const __nv_bfloat16* __restrict__ xw,
                             const int* __restrict__ csrc, const int* __restrict__ off,
                             const float* __restrict__ rsd, const float* __restrict__ din,
                             const float* __restrict__ bias,
                             float* outf, __nv_bfloat16* outh, int n, int relu) {
    int d = (blockIdx.x * blockDim.x + threadIdx.x) >> 5;
    int lane = threadIdx.x & 31;
    if (d >= n) return;
    float acc[8] = {};
    int p0 = off[d], p1 = off[d + 1];
    int p = p0;
    for (; p + 4 <= p1; p += 4) {
        int s0 = __ldg(csrc + p), s1i = __ldg(csrc + p + 1);
        int s2i = __ldg(csrc + p + 2), s3i = __ldg(csrc + p + 3);
        float w0 = rsd[s0], w1 = rsd[s1i], w2 = rsd[s2i], w3 = rsd[s3i];
        uint4 v0 = *((const uint4*)(xw + (size_t)s0 * D) + lane);
        uint4 v1 = *((const uint4*)(xw + (size_t)s1i * D) + lane);
        uint4 v2 = *((const uint4*)(xw + (size_t)s2i * D) + lane);
        uint4 v3 = *((const uint4*)(xw + (size_t)s3i * D) + lane);
        const __nv_bfloat16* h0 = (const __nv_bfloat16*)&v0;
        const __nv_bfloat16* h1 = (const __nv_bfloat16*)&v1;
        const __nv_bfloat16* h2 = (const __nv_bfloat16*)&v2;
        const __nv_bfloat16* h3 = (const __nv_bfloat16*)&v3;
#pragma unroll
        for (int k = 0; k < 8; k++)
            acc[k] += __bfloat162float(h0[k]) * w0 + __bfloat162float(h1[k]) * w1 +
                      __bfloat162float(h2[k]) * w2 + __bfloat162float(h3[k]) * w3;
    }
    for (; p < p1; p++) {
        int s = __ldg(csrc + p);
        float w = rsd[s];
        uint4 v = *((const uint4*)(xw + (size_t)s * D) + lane);
        const __nv_bfloat16* hv = (const __nv_bfloat16*)&v;
#pragma unroll
        for (int k = 0; k < 8; k++) acc[k] += __bfloat162float(hv[k]) * w;
    }
    float sc = rsqrtf(din[d]);
    int col = lane * 8;
    float o[8];
#pragma unroll
    for (int k = 0; k < 8; k++) {
        float v = acc[k] * sc + bias[col + k];
        o[k] = relu ? fmaxf(v, 0.f) : v;
    }
    if (outf) {
        float4* fr = (float4*)(outf + (size_t)d * D + col);
        fr[0] = make_float4(o[0], o[1], o[2], o[3]);
        fr[1] = make_float4(o[4], o[5], o[6], o[7]);
    }
    if (outh) {
        __nv_bfloat16 hb[8];
#pragma unroll
        for (int k = 0; k < 8; k++) hb[k] = __float2bfloat16(o[k]);
        *(uint4*)(outh + (size_t)d * D + col) = *(uint4*)hb;
    }
}

__global__ void bnstat_k(const float* __restrict__ t, float* musum, float* varsum, int M) {
    int col = threadIdx.x;
    int rpb = (M + gridDim.x - 1) / gridDim.x;
    int r0 = blockIdx.x * rpb;
    int r1 = min(r0 + rpb, M);
    float s = 0.f, s2 = 0.f;
    for (int r = r0; r < r1; r++) {
        float v = t[(size_t)r * D + col];
        s += v; s2 += v * v;
    }
    atomicAdd(&musum[col], s);
    atomicAdd(&varsum[col], s2);
}

__global__ void bnapply_k(const float* __restrict__ t, const float* __restrict__ musum,
                          const float* __restrict__ varsum,
                          const float* __restrict__ gamma, const float* __restrict__ beta,
                          __nv_bfloat16* th, int M) {
    int i = blockIdx.x * blockDim.x + threadIdx.x;
    if (i < M * D) {
        int c = i & (D - 1);
        float mu = musum[c] / M;
        float var = varsum[c] / M - mu * mu;
        float v = (t[i] - mu) * rsqrtf(var + BN_EPS) * gamma[c] + beta[c];
        th[i] = __float2bfloat16(fmaxf(v, 0.f));
    }
}

// both normalizations in one launch: blockIdx.y selects (h->z,zh) or (p->q,qh)
__global__ void norml2_k(const float* __restrict__ x0, float* __restrict__ z0,
                         __nv_bfloat16* __restrict__ zh0,
                         const float* __restrict__ x1, float* __restrict__ z1,
                         __nv_bfloat16* __restrict__ zh1, int M, int Mpad) {
    const float* x = blockIdx.y ? x1 : x0;
    float* z = blockIdx.y ? z1 : z0;
    __nv_bfloat16* zh = blockIdx.y ? zh1 : zh0;
    int row = (blockIdx.x * blockDim.x + threadIdx.x) >> 5;
    int lane = threadIdx.x & 31;
    if (row >= Mpad) return;
    __nv_bfloat16* hr = zh + (size_t)row * D;
    if (row >= M) {
#pragma unroll
        for (int c = 0; c < D / 32; c++) hr[lane + 32 * c] = __float2bfloat16(0.f);
        return;
    }
    const float* xr = x + (size_t)row * D;
    float s = 0.f;
#pragma unroll
    for (int c = 0; c < D / 32; c++) {
        float v = xr[lane + 32 * c];
        s += v * v;
    }
#pragma unroll
    for (int o = 16; o > 0; o >>= 1) s += __shfl_xor_sync(0xffffffffu, s, o);
    float inv = 1.f / fmaxf(sqrtf(s), 1e-12f);
    float* zr = z + (size_t)row * D;
#pragma unroll
    for (int c = 0; c < D / 32; c++) {
        int f = lane + 32 * c;
        float v = xr[f] * inv;
        zr[f] = v;
        hr[f] = __float2bfloat16(v);
    }
}

// pos gather with bf16 z and q, unroll-4
__global__ void gather_pos_k(const __nv_bfloat16* __restrict__ zh,
                             const __nv_bfloat16* __restrict__ qh,
                             const int* __restrict__ csrc, const int* __restrict__ off,
                             float* pos, int n) {
    int d = (blockIdx.x * blockDim.x + threadIdx.x) >> 5;
    int lane = threadIdx.x & 31;
    if (d >= n) return;
    uint4 qv = *((const uint4*)(qh + (size_t)d * D) + lane);
    const __nv_bfloat16* qe = (const __nv_bfloat16*)&qv;
    float qf[8];
#pragma unroll
    for (int k = 0; k < 8; k++) qf[k] = __bfloat162float(qe[k]);
    float sz[8] = {};
    int p0 = off[d], p1 = off[d + 1];
    int p = p0;
    for (; p + 4 <= p1; p += 4) {
        int s0 = __ldg(csrc + p), s1i = __ldg(csrc + p + 1);
        int s2i = __ldg(csrc + p + 2), s3i = __ldg(csrc + p + 3);
        uint4 v0 = *((const uint4*)(zh + (size_t)s0 * D) + lane);
        uint4 v1 = *((const uint4*)(zh + (size_t)s1i * D) + lane);
        uint4 v2 = *((const uint4*)(zh + (size_t)s2i * D) + lane);
        uint4 v3 = *((const uint4*)(zh + (size_t)s3i * D) + lane);
        const __nv_bfloat16* h0 = (const __nv_bfloat16*)&v0;
        const __nv_bfloat16* h1 = (const __nv_bfloat16*)&v1;
        const __nv_bfloat16* h2 = (const __nv_bfloat16*)&v2;
        const __nv_bfloat16* h3 = (const __nv_bfloat16*)&v3;
#pragma unroll
        for (int k = 0; k < 8; k++)
            sz[k] += __bfloat162float(h0[k]) + __bfloat162float(h1[k]) +
                     __bfloat162float(h2[k]) + __bfloat162float(h3[k]);
    }
    for (; p < p1; p++) {
        int s = __ldg(csrc + p);
        uint4 v = *((const uint4*)(zh + (size_t)s * D) + lane);
        const __nv_bfloat16* hv = (const __nv_bfloat16*)&v;
#pragma unroll
        for (int k = 0; k < 8; k++) sz[k] += __bfloat162float(hv[k]);
    }
    float dot = 0.f;
#pragma unroll
    for (int k = 0; k < 8; k++) dot += sz[k] * qf[k];
#pragma unroll
    for (int o = 16; o > 0; o >>= 1) dot += __shfl_xor_sync(0xffffffffu, dot, o);
    if (lane == 0) pos[d] = dot * TEMP_INV;
}

// fused mneg + loss: per d: v = (sum_p log(s1[d]+LAM*s2[src_p]) - pos[d]) / deg_d
// block-reduce, one atomic per block into out (out pre-zeroed)
__global__ void mneg_loss_k(const float* __restrict__ s1, const float* __restrict__ s2,
                            const float* __restrict__ pos,
                            const int* __restrict__ csrc, const int* __restrict__ off,
                            float* out, int n) {
    __shared__ float ws[8];
    int tid = threadIdx.x;
    int lane = tid & 31, warp = tid >> 5;
    int d = (blockIdx.x * blockDim.x + tid) >> 5;
    float contrib = 0.f;
    if (d < n) {
        float base = s1[d];
        float acc = 0.f;
        int p0 = off[d], p1 = off[d + 1];
        for (int p = p0 + lane; p < p1; p += 32)
            acc += __logf(base + LAM * s2[__ldg(csrc + p)]);
#pragma unroll
        for (int o = 16; o > 0; o >>= 1) acc += __shfl_xor_sync(0xffffffffu, acc, o);
        if (lane == 0) contrib = (acc - pos[d]) / (float)(p1 - p0);
    }
    if (lane == 0) ws[warp] = contrib;
    __syncthreads();
    if (tid == 0) {
        float t = 0.f;
#pragma unroll
        for (int w = 0; w < 8; w++) t += ws[w];
        atomicAdd(out, t / n);
    }
}

// ---------------- mma helpers ----------------
__device__ __forceinline__ void ldsm4(uint32_t addr, uint32_t& r0, uint32_t& r1,
                                      uint32_t& r2, uint32_t& r3) {
    asm volatile("ldmatrix.sync.aligned.m8n8.x4.shared.b16 {%0,%1,%2,%3}, [%4];"
                 : "=r"(r0), "=r"(r1), "=r"(r2), "=r"(r3) : "r"(addr));
}
__device__ __forceinline__ void mma16816(float* c, const uint32_t* a,
                                         uint32_t b0, uint32_t b1) {
    asm volatile(
        "mma.sync.aligned.m16n8k16.row.col.f32.bf16.bf16.f32 "
        "{%0,%1,%2,%3}, {%4,%5,%6,%7}, {%8,%9}, {%0,%1,%2,%3};"
        : "+f"(c[0]), "+f"(c[1]), "+f"(c[2]), "+f"(c[3])
        : "r"(a[0]), "r"(a[1]), "r"(a[2]), "r"(a[3]), "r"(b0), "r"(b1));
}
__device__ __forceinline__ void cp16(uint32_t saddr, const void* g) {
    asm volatile("cp.async.cg.shared.global [%0], [%1], 16;"
                 :: "r"(saddr), "l"(g) : "memory");
}
// load one 128x64 bf16 tile into smem (SW128 row swizzle), 256 threads
__device__ __forceinline__ void loadB64(uint32_t sdst, const __nv_bfloat16* Bg,
                                        int k0, int ldb, int tid) {
#pragma unroll
    for (int t = 0; t < 4; t++) {
        int c = tid + t * 256;
        int row = c >> 3, ch = c & 7;
        uint32_t off = (uint32_t)(row * 128 + ((ch ^ (row & 7)) << 4));
        cp16(sdst + off, Bg + (size_t)row * ldb + k0 + ch * 8);
    }
    asm volatile("cp.async.commit_group;" ::: "memory");
}

#define STAGE_BYTES 32768

// ---------------- bf16 tensor GEMM (pipelined): C = A[Mpad,K] @ Wt[256,K]^T ----------------
__global__ __launch_bounds__(256, 2) void gemm_bf16_k(
    const __nv_bfloat16* __restrict__ A, const __nv_bfloat16* __restrict__ Wt,
    const float* __restrict__ bias, float* __restrict__ Cf,
    __nv_bfloat16* __restrict__ Ch, int M, int K, int relu) {
    extern __shared__ char dsm[];
    uint32_t sbase = (uint32_t)__cvta_generic_to_shared(dsm);
    int tid = threadIdx.x;
    int lane = tid & 31, warp = tid >> 5;
    int wi = warp >> 1, wj = warp & 1;
    int i0 = blockIdx.x * 128, j0 = blockIdx.y * 128;

    int a_row = (lane & 15);
    int a_chsel = (lane >> 4);
    int b_row = (lane & 7) + ((lane >> 4) & 1) * 8;
    int b_chsel = ((lane >> 3) & 1);

    const __nv_bfloat16* Ag = A + (size_t)i0 * K;
    const __nv_bfloat16* Bg = Wt + (size_t)j0 * K;

    float acc[2][8][4];
#pragma unroll
    for (int x = 0; x < 2; x++)
#pragma unroll
        for (int y = 0; y < 8; y++)
#pragma unroll
            for (int v = 0; v < 4; v++) acc[x][y][v] = 0.f;

    int KT = K >> 6;
    loadB64(sbase, Ag, 0, K, tid);
    loadB64(sbase + 16384, Bg, 0, K, tid);
    for (int kt = 0; kt < KT; kt++) {
        asm volatile("cp.async.wait_group 0;" ::: "memory");
        __syncthreads();
        if (kt + 1 < KT) {
            uint32_t sa = sbase + ((kt + 1) & 1) * STAGE_BYTES;
            loadB64(sa, Ag, (kt + 1) * 64, K, tid);
            loadB64(sa + 16384, Bg, (kt + 1) * 64, K, tid);
        }
        uint32_t sAu = sbase + (kt & 1) * STAGE_BYTES;
        uint32_t sBu = sAu + 16384;
#pragma unroll
        for (int ks = 0; ks < 4; ks++) {
            uint32_t afr[2][4];
#pragma unroll
            for (int mt = 0; mt < 2; mt++) {
                int row = wi * 32 + mt * 16 + a_row;
                int ch = ks * 2 + a_chsel;
                uint32_t addr = sAu + (uint32_t)(row * 128 + ((ch ^ (row & 7)) << 4));
                ldsm4(addr, afr[mt][0], afr[mt][1], afr[mt][2], afr[mt][3]);
            }
#pragma unroll
            for (int p = 0; p < 4; p++) {
                int nrow = wj * 64 + p * 16 + b_row;
                int ch = ks * 2 + b_chsel;
                uint32_t addr = sBu + (uint32_t)(nrow * 128 + ((ch ^ (nrow & 7)) << 4));
                uint32_t bf0, bf1, bf2, bf3;
                ldsm4(addr, bf0, bf1, bf2, bf3);
#pragma unroll
                for (int mt = 0; mt < 2; mt++) {
                    mma16816(acc[mt][2 * p], afr[mt], bf0, bf1);
                    mma16816(acc[mt][2 * p + 1], afr[mt], bf2, bf3);
                }
            }
        }
        __syncthreads();
    }
#pragma unroll
    for (int mt = 0; mt < 2; mt++) {
        int r0 = i0 + wi * 32 + mt * 16 + (lane >> 2);
#pragma unroll
        for (int nt = 0; nt < 8; nt++) {
            int col = j0 + wj * 64 + nt * 8 + (lane & 3) * 2;
            float b0 = bias ? bias[col] : 0.f;
            float b1 = bias ? bias[col + 1] : 0.f;
            float v0 = acc[mt][nt][0] + b0, v1 = acc[mt][nt][1] + b1;
            float v2 = acc[mt][nt][2] + b0, v3 = acc[mt][nt][3] + b1;
            if (relu) {
                v0 = fmaxf(v0, 0.f); v1 = fmaxf(v1, 0.f);
                v2 = fmaxf(v2, 0.f); v3 = fmaxf(v3, 0.f);
            }
            if (r0 < M) {
                if (Cf) { Cf[(size_t)r0 * D + col] = v0; Cf[(size_t)r0 * D + col + 1] = v1; }
                if (Ch) {
                    Ch[(size_t)r0 * D + col] = __float2bfloat16(v0);
                    Ch[(size_t)r0 * D + col + 1] = __float2bfloat16(v1);
                }
            }
            int r1 = r0 + 8;
            if (r1 < M) {
                if (Cf) { Cf[(size_t)r1 * D + col] = v2; Cf[(size_t)r1 * D + col + 1] = v3; }
                if (Ch) {
                    Ch[(size_t)r1 * D + col] = __float2bfloat16(v2);
                    Ch[(size_t)r1 * D + col + 1] = __float2bfloat16(v3);
                }
            }
        }
    }
}

// ---------------- fused dual negsum: s1 += rowsum exp(2 z.z'), s2 += rowsum exp(2 z.q') ----------------
// A tile (zh rows i0..i0+127, K=256) resident in smem (4 blocked 128x64 SW128 tiles).
// B stages double-buffered; per j-tile process B=zh then B=qh.
__global__ __launch_bounds__(256, 2) void negmma2_k(
    const __nv_bfloat16* __restrict__ Z, const __nv_bfloat16* __restrict__ Q,
    float* __restrict__ s1, float* __restrict__ s2, int n, int nJT) {
    extern __shared__ char dsm[];
    uint32_t aBase = (uint32_t)__cvta_generic_to_shared(dsm);        // 65536 B
    uint32_t bBase = aBase + 65536;                                   // 2 x 16384 B
    int tid = threadIdx.x;
    int lane = tid & 31, warp = tid >> 5;
    int wi = warp >> 1, wj = warp & 1;
    int i0 = blockIdx.x * 128;

    int a_row = (lane & 15);
    int a_chsel = (lane >> 4);
    int b_row = (lane & 7) + ((lane >> 4) & 1) * 8;
    int b_chsel = ((lane >> 3) & 1);

    // resident A load: 4096 x 16B chunks, blocked [4][128 rows][8 ch]
#pragma unroll
    for (int t = 0; t < 16; t++) {
        int c = tid + t * 256;
        int blk = c >> 10, idx = c & 1023;
        int row = idx >> 3, ch = idx & 7;
        uint32_t off = (uint32_t)(blk * 16384 + row * 128 + ((ch ^ (row & 7)) << 4));
        cp16(aBase + off, Z + (size_t)(i0 + row) * D + blk * 64 + ch * 8);
    }
    asm volatile("cp.async.commit_group;" ::: "memory");

    float rs[2][2][2];  // [sel][mt][h]
#pragma unroll
    for (int a = 0; a < 2; a++)
#pragma unroll
        for (int b = 0; b < 2; b++)
#pragma unroll
            for (int c = 0; c < 2; c++) rs[a][b][c] = 0.f;

    for (int jt = blockIdx.y; jt < nJT; jt += gridDim.y) {
        int j0 = jt * 128;
#pragma unroll 1
        for (int sel = 0; sel < 2; sel++) {
            const __nv_bfloat16* Bg = (sel ? Q : Z) + (size_t)j0 * D;
            loadB64(bBase, Bg, 0, D, tid);
            float acc[2][8][4];
#pragma unroll
            for (int x = 0; x < 2; x++)
#pragma unroll
                for (int y = 0; y < 8; y++)
#pragma unroll
                    for (int v = 0; v < 4; v++) acc[x][y][v] = 0.f;

#pragma unroll
            for (int kt = 0; kt < 4; kt++) {
                asm volatile("cp.async.wait_group 0;" ::: "memory");
                __syncthreads();
                if (kt < 3) loadB64(bBase + ((kt + 1) & 1) * 16384, Bg, (kt + 1) * 64, D, tid);
                uint32_t sAu = aBase + kt * 16384;
                uint32_t sBu = bBase + (kt & 1) * 16384;
#pragma unroll
                for (int ks = 0; ks < 4; ks++) {
                    uint32_t afr[2][4];
#pragma unroll
                    for (int mt = 0; mt < 2; mt++) {
                        int row = wi * 32 + mt * 16 + a_row;
                        int ch = ks * 2 + a_chsel;
                        uint32_t addr = sAu + (uint32_t)(row * 128 + ((ch ^ (row & 7)) << 4));
                        ldsm4(addr, afr[mt][0], afr[mt][1], afr[mt][2], afr[mt][3]);
                    }
#pragma unroll
                    for (int p = 0; p < 4; p++) {
                        int nrow = wj * 64 + p * 16 + b_row;
                        int ch = ks * 2 + b_chsel;
                        uint32_t addr = sBu + (uint32_t)(nrow * 128 + ((ch ^ (nrow & 7)) << 4));
                        uint32_t bf0, bf1, bf2, bf3;
                        ldsm4(addr, bf0, bf1, bf2, bf3);
#pragma unroll
                        for (int mt = 0; mt < 2; mt++) {
                            mma16816(acc[mt][2 * p], afr[mt], bf0, bf1);
                            mma16816(acc[mt][2 * p + 1], afr[mt], bf2, bf3);
                        }
                    }
                }
                __syncthreads();
            }
            // epilogue: exp + masked rowsum
#pragma unroll
            for (int mt = 0; mt < 2; mt++) {
#pragma unroll
                for (int nt = 0; nt < 8; nt++) {
                    int j = j0 + wj * 64 + nt * 8 + (lane & 3) * 2;
                    float e0 = (j < n) ? __expf(acc[mt][nt][0] * TEMP_INV) : 0.f;
                    float e1 = (j + 1 < n) ? __expf(acc[mt][nt][1] * TEMP_INV) : 0.f;
                    float e2 = (j < n) ? __expf(acc[mt][nt][2] * TEMP_INV) : 0.f;
                    float e3 = (j + 1 < n) ? __expf(acc[mt][nt][3] * TEMP_INV) : 0.f;
                    rs[sel][mt][0] += e0 + e1;
                    rs[sel][mt][1] += e2 + e3;
                }
            }
        }
    }
#pragma unroll
    for (int sel = 0; sel < 2; sel++) {
        float* out = sel ? s2 : s1;
#pragma unroll
        for (int mt = 0; mt < 2; mt++) {
#pragma unroll
            for (int h = 0; h < 2; h++) {
                float v = rs[sel][mt][h];
                v += __shfl_xor_sync(0xffffffffu, v, 1);
                v += __shfl_xor_sync(0xffffffffu, v, 2);
                if ((lane & 3) == 0) {
                    int i = i0 + wi * 32 + mt * 16 + h * 8 + (lane >> 2);
                    if (i < n) atomicAdd(&out[i], v);
                }
            }
        }
    }
}

// ------------------------------ launcher ------------------------------
static float* symf(const void* s) { void* p = nullptr; cudaGetSymbolAddress(&p, s); return (float*)p; }
static int* symi(const void* s) { void* p = nullptr; cudaGetSymbolAddress(&p, s); return (int*)p; }
static __nv_bfloat16* symh(const void* s) { void* p = nullptr; cudaGetSymbolAddress(&p, s); return (__nv_bfloat16*)p; }

extern "C" void kernel_launch(void* const* d_in, const int* in_sizes, int n_in,
                              void* d_out, int out_size) {
    const float* feat  = (const float*)d_in[0];
    const float* W1    = (const float*)d_in[1];
    const float* b1    = (const float*)d_in[2];
    const float* W2    = (const float*)d_in[3];
    const float* b2    = (const float*)d_in[4];
    const float* Wt1   = (const float*)d_in[5];
    const float* bt1   = (const float*)d_in[6];
    const float* gamma = (const float*)d_in[7];
    const float* beta  = (const float*)d_in[8];
    const float* Wt2   = (const float*)d_in[9];
    const float* bt2   = (const float*)d_in[10];
    const float* Wp    = (const float*)d_in[11];
    const float* bp    = (const float*)d_in[12];
    const int*   src   = (const int*)d_in[13];
    const int*   dst   = (const int*)d_in[14];

    const int IN = 512;
    int n = in_sizes[0] / IN;
    int e = in_sizes[13];
    int nTI = (n + 127) / 128;
    int npad = nTI * 128;

    float* tbuf = symf(g_t);
    float* hbuf = symf(g_h);
    float* pbuf = symf(g_p);
    float* zbuf = symf(g_z);
    float* qbuf = symf(g_q);
    __nv_bfloat16* featb = symh(g_featb);
    __nv_bfloat16* xwb = symh(g_xwb);
    __nv_bfloat16* h1b = symh(g_h1b);
    __nv_bfloat16* tb = symh(g_tb);
    __nv_bfloat16* transb = symh(g_transb);
    __nv_bfloat16* zh = symh(g_zh);
    __nv_bfloat16* qh = symh(g_qh);
    __nv_bfloat16* W1b = symh(g_W1b);
    __nv_bfloat16* W2b = symh(g_W2b);
    __nv_bfloat16* Wt1b = symh(g_Wt1b);
    __nv_bfloat16* Wt2b = symh(g_Wt2b);
    __nv_bfloat16* Wpb = symh(g_Wpb);
    float* dout = symf(g_degout);
    float* din  = symf(g_degin);
    float* rsd  = symf(g_rsd);
    int* cnt = symi(g_cnt);
    int* off = symi(g_off);
    int* cur = symi(g_cur);
    int* csrc = symi(g_csrc);
    float* musum = symf(g_musum);
    float* varsum = symf(g_varsum);
    float* s1 = symf(g_s1);
    float* s2 = symf(g_s2);
    float* pos = symf(g_pos);
    float* out = (float*)d_out;

    int nd = n * D;
    int ndpad = npad * D;
    int tail = ndpad - nd;
    dim3 gemm_grid(nTI, 2);
    int node_warp_blocks = (n * 32 + 255) / 256;

    cudaFuncSetAttribute(gemm_bf16_k, cudaFuncAttributeMaxDynamicSharedMemorySize, 2 * STAGE_BYTES);
    cudaFuncSetAttribute(negmma2_k, cudaFuncAttributeMaxDynamicSharedMemorySize, 98304);

    // conversions
    f2b_k<<<(npad * IN + 255) / 256, 256>>>(feat, featb, n * IN, npad * IN);
    wconvall_k<<<(458752 + 255) / 256, 256>>>(W1, Wt1, W2, Wt2, Wp,
                                              W1b, Wt1b, W2b, Wt2b, Wpb);

    // degrees + CSR by dst
    zero3_k<<<(n + 255) / 256, 256>>>(dout, din, cnt, n);
    degree_k<<<(e + 255) / 256, 256>>>(src, dst, dout, din, cnt, e);
    rsdcur_k<<<(n + 255) / 256, 256>>>(dout, rsd, cur, n);
    scan_k<<<1, 1024>>>(cnt, off, n);
    fillcsr_k<<<(e + 255) / 256, 256>>>(src, dst, off, cur, csrc, e);

    // GCN layer 1
    gemm_bf16_k<<<gemm_grid, 256, 2 * STAGE_BYTES>>>(featb, W1b, nullptr, nullptr, xwb, n, IN, 0);
    gather_agg_k<<<node_warp_blocks, 256>>>(xwb, csrc, off, rsd, din, b1, nullptr, h1b, n, 1);
    zerohtail_k<<<(tail + 255) / 256, 256>>>(h1b, nd, ndpad);

    // GCN layer 2
    gemm_bf16_k<<<gemm_grid, 256, 2 * STAGE_BYTES>>>(h1b, W2b, nullptr, nullptr, xwb, n, D, 0);
    gather_agg_k<<<node_warp_blocks, 256>>>(xwb, csrc, off, rsd, din, b2, hbuf, nullptr, n, 0);

    // target MLP
    gemm_bf16_k<<<gemm_grid, 256, 2 * STAGE_BYTES>>>(featb, Wt1b, bt1, tbuf, nullptr, n, IN, 0);
    zero2_k<<<1, 256>>>(musum, varsum, D);
    bnstat_k<<<100, 256>>>(tbuf, musum, varsum, n);
    bnapply_k<<<(nd + 255) / 256, 256>>>(tbuf, musum, varsum, gamma, beta, tb, n);
    zerohtail_k<<<(tail + 255) / 256, 256>>>(tb, nd, ndpad);
    gemm_bf16_k<<<gemm_grid, 256, 2 * STAGE_BYTES>>>(tb, Wt2b, bt2, nullptr, transb, n, D, 0);
    zerohtail_k<<<(tail + 255) / 256, 256>>>(transb, nd, ndpad);
    gemm_bf16_k<<<gemm_grid, 256, 2 * STAGE_BYTES>>>(transb, Wpb, bp, pbuf, nullptr, n, D, 0);

    // normalize both
    dim3 norm_grid((npad * 32 + 255) / 256, 2);
    norml2_k<<<norm_grid, 256>>>(hbuf, zbuf, zh, pbuf, qbuf, qh, n, npad);

    // pos (gather, bf16)
    gather_pos_k<<<node_warp_blocks, 256>>>(zh, qh, csrc, off, pos, n);

    // fused dual negsum
    zero2_k<<<(n + 255) / 256, 256>>>(s1, s2, n);
    dim3 neg_grid(nTI, 8);
    negmma2_k<<<neg_grid, 256, 98304>>>(zh, qh, s1, s2, n, nTI);

    // fused mneg + loss
    zero_k<<<1, 32>>>(out, out_size);
    mneg_loss_k<<<node_warp_blocks, 256>>>(s1, s2, pos, csrc, off, out, n);
}

// round 8
// speedup vs baseline: 15.8090x; 1.2204x over previous
#include <cuda_runtime.h>
#include <cuda_bf16.h>
#include <stdint.h>
#include <math.h>

#define NMAX 10240
#define EMAX 340000
#define D 256
#define INMAX 512
#define TEMP_INV 2.0f
#define LAM 1e-3f
#define BN_EPS 1e-5f

// ------------------------------ scratch ------------------------------
__device__ __align__(16) float g_t[NMAX * D];
__device__ __align__(16) float g_h[NMAX * D];
__device__ __align__(16) float g_p[NMAX * D];
__device__ __align__(16) float g_z[NMAX * D];
__device__ __align__(16) float g_q[NMAX * D];
__device__ __align__(16) __nv_bfloat16 g_featb[NMAX * INMAX];
__device__ __align__(16) __nv_bfloat16 g_xwb[NMAX * D];
__device__ __align__(16) __nv_bfloat16 g_h1b[NMAX * D];
__device__ __align__(16) __nv_bfloat16 g_tb[NMAX * D];
__device__ __align__(16) __nv_bfloat16 g_transb[NMAX * D];
__device__ __align__(16) __nv_bfloat16 g_zh[NMAX * D];
__device__ __align__(16) __nv_bfloat16 g_qh[NMAX * D];
__device__ __align__(16) __nv_bfloat16 g_W1b[INMAX * D];
__device__ __align__(16) __nv_bfloat16 g_W2b[D * D];
__device__ __align__(16) __nv_bfloat16 g_Wt1b[INMAX * D];
__device__ __align__(16) __nv_bfloat16 g_Wt2b[D * D];
__device__ __align__(16) __nv_bfloat16 g_Wpb[D * D];
__device__ float g_degout[NMAX];
__device__ float g_degin[NMAX];
__device__ float g_rsd[NMAX];
__device__ int   g_cnt[NMAX];
__device__ int   g_off[NMAX + 1];
__device__ int   g_cur[NMAX];
__device__ int   g_csrc[EMAX];
__device__ float g_musum[D];
__device__ float g_varsum[D];
__device__ float g_s1[NMAX];
__device__ float g_s2[NMAX];
__device__ float g_pos[NMAX];

// ------------------------------ small kernels ------------------------------
__global__ void zero2_k(float* a, float* b, int n) {
    int i = blockIdx.x * blockDim.x + threadIdx.x;
    if (i < n) { a[i] = 0.f; b[i] = 0.f; }
}
__global__ void zero3_k(float* a, float* b, int* c, int n) {
    int i = blockIdx.x * blockDim.x + threadIdx.x;
    if (i < n) { a[i] = 0.f; b[i] = 0.f; c[i] = 0; }
}
__global__ void zero_k(float* p, int n) {
    int i = blockIdx.x * blockDim.x + threadIdx.x;
    if (i < n) p[i] = 0.f;
}

__global__ void f2b_k(const float* __restrict__ x, __nv_bfloat16* __restrict__ y,
                      int n, int ntot) {
    int i = blockIdx.x * blockDim.x + threadIdx.x;
    if (i < ntot) y[i] = __float2bfloat16(i < n ? x[i] : 0.f);
}

__global__ void wconvall_k(const float* W1, const float* Wt1,
                           const float* W2, const float* Wt2, const float* Wp,
                           __nv_bfloat16* W1b, __nv_bfloat16* Wt1b,
                           __nv_bfloat16* W2b, __nv_bfloat16* Wt2b,
                           __nv_bfloat16* Wpb) {
    int i = blockIdx.x * blockDim.x + threadIdx.x;
    const float* W; __nv_bfloat16* O; int K, li;
    if (i < 131072)        { W = W1;  O = W1b;  K = 512; li = i; }
    else if (i < 262144)   { W = Wt1; O = Wt1b; K = 512; li = i - 131072; }
    else if (i < 327680)   { W = W2;  O = W2b;  K = 256; li = i - 262144; }
    else if (i < 393216)   { W = Wt2; O = Wt2b; K = 256; li = i - 327680; }
    else if (i < 458752)   { W = Wp;  O = Wpb;  K = 256; li = i - 393216; }
    else return;
    int k = li >> 8, n = li & 255;
    O[n * K + k] = __float2bfloat16(W[(size_t)k * 256 + n]);
}

__global__ void zerohtail_k(__nv_bfloat16* p, int from, int to) {
    int i = from + blockIdx.x * blockDim.x + threadIdx.x;
    if (i < to) p[i] = __float2bfloat16(0.f);
}

__global__ void degree_k(const int* __restrict__ src, const int* __restrict__ dst,
                         float* dout, float* din, int* cnt, int e) {
    int i = blockIdx.x * blockDim.x + threadIdx.x;
    if (i < e) {
        atomicAdd(&dout[src[i]], 1.f);
        atomicAdd(&din[dst[i]], 1.f);
        atomicAdd(&cnt[dst[i]], 1);
    }
}

__global__ void rsdcur_k(const float* __restrict__ dout, float* rsd, int* cur, int n) {
    int i = blockIdx.x * blockDim.x + threadIdx.x;
    if (i < n) { rsd[i] = rsqrtf(dout[i]); cur[i] = 0; }
}

__global__ void scan_k(const int* __restrict__ cnt, int* off, int n) {
    __shared__ int ts[1024];
    int t = threadIdx.x;
    int L = (n + 1023) >> 10;
    int b = t * L, eidx = min(b + L, n);
    int s = 0;
    for (int i = b; i < eidx; i++) s += cnt[i];
    ts[t] = s;
    __syncthreads();
    for (int d2 = 1; d2 < 1024; d2 <<= 1) {
        int v = (t >= d2) ? ts[t - d2] : 0;
        __syncthreads();
        ts[t] += v;
        __syncthreads();
    }
    int base = (t == 0) ? 0 : ts[t - 1];
    for (int i = b; i < eidx; i++) { off[i] = base; base += cnt[i]; }
    if (t == 1023) off[n] = ts[1023];
}

__global__ void fillcsr_k(const int* __restrict__ src, const int* __restrict__ dst,
                          const int* __restrict__ off, int* cur, int* csrc, int e) {
    int i = blockIdx.x * blockDim.x + threadIdx.x;
    if (i < e) {
        int d = dst[i];
        int p = off[d] + atomicAdd(&cur[d], 1);
        csrc[p] = src[i];
    }
}

__global__ void gather_agg_k(const __nv_bfloat16* __restrict__ xw,
                             const int* __restrict__ csrc, const int* __restrict__ off,
                             const float* __restrict__ rsd, const float* __restrict__ din,
                             const float* __restrict__ bias,
                             float* outf, __nv_bfloat16* outh, int n, int relu) {
    int d = (blockIdx.x * blockDim.x + threadIdx.x) >> 5;
    int lane = threadIdx.x & 31;
    if (d >= n) return;
    float acc[8] = {};
    int p0 = off[d], p1 = off[d + 1];
    int p = p0;
    for (; p + 4 <= p1; p += 4) {
        int s0 = __ldg(csrc + p), s1i = __ldg(csrc + p + 1);
        int s2i = __ldg(csrc + p + 2), s3i = __ldg(csrc + p + 3);
        float w0 = rsd[s0], w1 = rsd[s1i], w2 = rsd[s2i], w3 = rsd[s3i];
        uint4 v0 = *((const uint4*)(xw + (size_t)s0 * D) + lane);
        uint4 v1 = *((const uint4*)(xw + (size_t)s1i * D) + lane);
        uint4 v2 = *((const uint4*)(xw + (size_t)s2i * D) + lane);
        uint4 v3 = *((const uint4*)(xw + (size_t)s3i * D) + lane);
        const __nv_bfloat16* h0 = (const __nv_bfloat16*)&v0;
        const __nv_bfloat16* h1 = (const __nv_bfloat16*)&v1;
        const __nv_bfloat16* h2 = (const __nv_bfloat16*)&v2;
        const __nv_bfloat16* h3 = (const __nv_bfloat16*)&v3;
#pragma unroll
        for (int k = 0; k < 8; k++)
            acc[k] += __bfloat162float(h0[k]) * w0 + __bfloat162float(h1[k]) * w1 +
                      __bfloat162float(h2[k]) * w2 + __bfloat162float(h3[k]) * w3;
    }
    for (; p < p1; p++) {
        int s = __ldg(csrc + p);
        float w = rsd[s];
        uint4 v = *((const uint4*)(xw + (size_t)s * D) + lane);
        const __nv_bfloat16* hv = (const __nv_bfloat16*)&v;
#pragma unroll
        for (int k = 0; k < 8; k++) acc[k] += __bfloat162float(hv[k]) * w;
    }
    float sc = rsqrtf(din[d]);
    int col = lane * 8;
    float o[8];
#pragma unroll
    for (int k = 0; k < 8; k++) {
        float v = acc[k] * sc + bias[col + k];
        o[k] = relu ? fmaxf(v, 0.f) : v;
    }
    if (outf) {
        float4* fr = (float4*)(outf + (size_t)d * D + col);
        fr[0] = make_float4(o[0], o[1], o[2], o[3]);
        fr[1] = make_float4(o[4], o[5], o[6], o[7]);
    }
    if (outh) {
        __nv_bfloat16 hb[8];
#pragma unroll
        for (int k = 0; k < 8; k++) hb[k] = __float2bfloat16(o[k]);
        *(uint4*)(outh + (size_t)d * D + col) = *(uint4*)hb;
    }
}

__global__ void bnstat_k(const float* __restrict__ t, float* musum, float* varsum, int M) {
    int col = threadIdx.x;
    int rpb = (M + gridDim.x - 1) / gridDim.x;
    int r0 = blockIdx.x * rpb;
    int r1 = min(r0 + rpb, M);
    float s = 0.f, s2 = 0.f;
    for (int r = r0; r < r1; r++) {
        float v = t[(size_t)r * D + col];
        s += v; s2 += v * v;
    }
    atomicAdd(&musum[col], s);
    atomicAdd(&varsum[col], s2);
}

__global__ void bnapply_k(const float* __restrict__ t, const float* __restrict__ musum,
                          const float* __restrict__ varsum,
                          const float* __restrict__ gamma, const float* __restrict__ beta,
                          __nv_bfloat16* th, int M) {
    int i = blockIdx.x * blockDim.x + threadIdx.x;
    if (i < M * D) {
        int c = i & (D - 1);
        float mu = musum[c] / M;
        float var = varsum[c] / M - mu * mu;
        float v = (t[i] - mu) * rsqrtf(var + BN_EPS) * gamma[c] + beta[c];
        th[i] = __float2bfloat16(fmaxf(v, 0.f));
    }
}

__global__ void norml2_k(const float* __restrict__ x0, float* __restrict__ z0,
                         __nv_bfloat16* __restrict__ zh0,
                         const float* __restrict__ x1, float* __restrict__ z1,
                         __nv_bfloat16* __restrict__ zh1, int M, int Mpad) {
    const float* x = blockIdx.y ? x1 : x0;
    float* z = blockIdx.y ? z1 : z0;
    __nv_bfloat16* zh = blockIdx.y ? zh1 : zh0;
    int row = (blockIdx.x * blockDim.x + threadIdx.x) >> 5;
    int lane = threadIdx.x & 31;
    if (row >= Mpad) return;
    __nv_bfloat16* hr = zh + (size_t)row * D;
    if (row >= M) {
#pragma unroll
        for (int c = 0; c < D / 32; c++) hr[lane + 32 * c] = __float2bfloat16(0.f);
        return;
    }
    const float* xr = x + (size_t)row * D;
    float s = 0.f;
#pragma unroll
    for (int c = 0; c < D / 32; c++) {
        float v = xr[lane + 32 * c];
        s += v * v;
    }
#pragma unroll
    for (int o = 16; o > 0; o >>= 1) s += __shfl_xor_sync(0xffffffffu, s, o);
    float inv = 1.f / fmaxf(sqrtf(s), 1e-12f);
    float* zr = z + (size_t)row * D;
#pragma unroll
    for (int c = 0; c < D / 32; c++) {
        int f = lane + 32 * c;
        float v = xr[f] * inv;
        zr[f] = v;
        hr[f] = __float2bfloat16(v);
    }
}

__global__ void gather_pos_k(const __nv_bfloat16* __restrict__ zh,
                             const __nv_bfloat16* __restrict__ qh,
                             const int* __restrict__ csrc, const int* __restrict__ off,
                             float* pos, int n) {
    int d = (blockIdx.x * blockDim.x + threadIdx.x) >> 5;
    int lane = threadIdx.x & 31;
    if (d >= n) return;
    uint4 qv = *((const uint4*)(qh + (size_t)d * D) + lane);
    const __nv_bfloat16* qe = (const __nv_bfloat16*)&qv;
    float qf[8];
#pragma unroll
    for (int k = 0; k < 8; k++) qf[k] = __bfloat162float(qe[k]);
    float sz[8] = {};
    int p0 = off[d], p1 = off[d + 1];
    int p = p0;
    for (; p + 4 <= p1; p += 4) {
        int s0 = __ldg(csrc + p), s1i = __ldg(csrc + p + 1);
        int s2i = __ldg(csrc + p + 2), s3i = __ldg(csrc + p + 3);
        uint4 v0 = *((const uint4*)(zh + (size_t)s0 * D) + lane);
        uint4 v1 = *((const uint4*)(zh + (size_t)s1i * D) + lane);
        uint4 v2 = *((const uint4*)(zh + (size_t)s2i * D) + lane);
        uint4 v3 = *((const uint4*)(zh + (size_t)s3i * D) + lane);
        const __nv_bfloat16* h0 = (const __nv_bfloat16*)&v0;
        const __nv_bfloat16* h1 = (const __nv_bfloat16*)&v1;
        const __nv_bfloat16* h2 = (const __nv_bfloat16*)&v2;
        const __nv_bfloat16* h3 = (const __nv_bfloat16*)&v3;
#pragma unroll
        for (int k = 0; k < 8; k++)
            sz[k] += __bfloat162float(h0[k]) + __bfloat162float(h1[k]) +
                     __bfloat162float(h2[k]) + __bfloat162float(h3[k]);
    }
    for (; p < p1; p++) {
        int s = __ldg(csrc + p);
        uint4 v = *((const uint4*)(zh + (size_t)s * D) + lane);
        const __nv_bfloat16* hv = (const __nv_bfloat16*)&v;
#pragma unroll
        for (int k = 0; k < 8; k++) sz[k] += __bfloat162float(hv[k]);
    }
    float dot = 0.f;
#pragma unroll
    for (int k = 0; k < 8; k++) dot += sz[k] * qf[k];
#pragma unroll
    for (int o = 16; o > 0; o >>= 1) dot += __shfl_xor_sync(0xffffffffu, dot, o);
    if (lane == 0) pos[d] = dot * TEMP_INV;
}

__global__ void mneg_loss_k(const float* __restrict__ s1, const float* __restrict__ s2,
                            const float* __restrict__ pos,
                            const int* __restrict__ csrc, const int* __restrict__ off,
                            float* out, int n) {
    __shared__ float ws[8];
    int tid = threadIdx.x;
    int lane = tid & 31, warp = tid >> 5;
    int d = (blockIdx.x * blockDim.x + tid) >> 5;
    float contrib = 0.f;
    if (d < n) {
        float base = s1[d];
        float acc = 0.f;
        int p0 = off[d], p1 = off[d + 1];
        for (int p = p0 + lane; p < p1; p += 32)
            acc += __logf(base + LAM * s2[__ldg(csrc + p)]);
#pragma unroll
        for (int o = 16; o > 0; o >>= 1) acc += __shfl_xor_sync(0xffffffffu, acc, o);
        if (lane == 0) contrib = (acc - pos[d]) / (float)(p1 - p0);
    }
    if (lane == 0) ws[warp] = contrib;
    __syncthreads();
    if (tid == 0) {
        float t = 0.f;
#pragma unroll
        for (int w = 0; w < 8; w++) t += ws[w];
        atomicAdd(out, t / n);
    }
}

// ---------------- mma helpers ----------------
__device__ __forceinline__ void ldsm4(uint32_t addr, uint32_t& r0, uint32_t& r1,
                                      uint32_t& r2, uint32_t& r3) {
    asm volatile("ldmatrix.sync.aligned.m8n8.x4.shared.b16 {%0,%1,%2,%3}, [%4];"
                 : "=r"(r0), "=r"(r1), "=r"(r2), "=r"(r3) : "r"(addr));
}
__device__ __forceinline__ void mma16816(float* c, const uint32_t* a,
                                         uint32_t b0, uint32_t b1) {
    asm volatile(
        "mma.sync.aligned.m16n8k16.row.col.f32.bf16.bf16.f32 "
        "{%0,%1,%2,%3}, {%4,%5,%6,%7}, {%8,%9}, {%0,%1,%2,%3};"
        : "+f"(c[0]), "+f"(c[1]), "+f"(c[2]), "+f"(c[3])
        : "r"(a[0]), "r"(a[1]), "r"(a[2]), "r"(a[3]), "r"(b0), "r"(b1));
}
__device__ __forceinline__ void cp16(uint32_t saddr, const void* g) {
    asm volatile("cp.async.cg.shared.global [%0], [%1], 16;"
                 :: "r"(saddr), "l"(g) : "memory");
}
__device__ __forceinline__ void loadB64(uint32_t sdst, const __nv_bfloat16* Bg,
                                        int k0, int ldb, int tid) {
#pragma unroll
    for (int t = 0; t < 4; t++) {
        int c = tid + t * 256;
        int row = c >> 3, ch = c & 7;
        uint32_t off = (uint32_t)(row * 128 + ((ch ^ (row & 7)) << 4));
        cp16(sdst + off, Bg + (size_t)row * ldb + k0 + ch * 8);
    }
    asm volatile("cp.async.commit_group;" ::: "memory");
}

#define STAGE_BYTES 32768

// ---------------- bf16 tensor GEMM (pipelined): C = A[Mpad,K] @ Wt[256,K]^T ----------------
__global__ __launch_bounds__(256, 2) void gemm_bf16_k(
    const __nv_bfloat16* __restrict__ A, const __nv_bfloat16* __restrict__ Wt,
    const float* __restrict__ bias, float* __restrict__ Cf,
    __nv_bfloat16* __restrict__ Ch, int M, int K, int relu) {
    extern __shared__ char dsm[];
    uint32_t sbase = (uint32_t)__cvta_generic_to_shared(dsm);
    int tid = threadIdx.x;
    int lane = tid & 31, warp = tid >> 5;
    int wi = warp >> 1, wj = warp & 1;
    int i0 = blockIdx.x * 128, j0 = blockIdx.y * 128;

    int a_row = (lane & 15);
    int a_chsel = (lane >> 4);
    int b_row = (lane & 7) + ((lane >> 4) & 1) * 8;
    int b_chsel = ((lane >> 3) & 1);

    const __nv_bfloat16* Ag = A + (size_t)i0 * K;
    const __nv_bfloat16* Bg = Wt + (size_t)j0 * K;

    float acc[2][8][4];
#pragma unroll
    for (int x = 0; x < 2; x++)
#pragma unroll
        for (int y = 0; y < 8; y++)
#pragma unroll
            for (int v = 0; v < 4; v++) acc[x][y][v] = 0.f;

    int KT = K >> 6;
    loadB64(sbase, Ag, 0, K, tid);
    loadB64(sbase + 16384, Bg, 0, K, tid);
    for (int kt = 0; kt < KT; kt++) {
        asm volatile("cp.async.wait_group 0;" ::: "memory");
        __syncthreads();
        if (kt + 1 < KT) {
            uint32_t sa = sbase + ((kt + 1) & 1) * STAGE_BYTES;
            loadB64(sa, Ag, (kt + 1) * 64, K, tid);
            loadB64(sa + 16384, Bg, (kt + 1) * 64, K, tid);
        }
        uint32_t sAu = sbase + (kt & 1) * STAGE_BYTES;
        uint32_t sBu = sAu + 16384;
#pragma unroll
        for (int ks = 0; ks < 4; ks++) {
            uint32_t afr[2][4];
#pragma unroll
            for (int mt = 0; mt < 2; mt++) {
                int row = wi * 32 + mt * 16 + a_row;
                int ch = ks * 2 + a_chsel;
                uint32_t addr = sAu + (uint32_t)(row * 128 + ((ch ^ (row & 7)) << 4));
                ldsm4(addr, afr[mt][0], afr[mt][1], afr[mt][2], afr[mt][3]);
            }
#pragma unroll
            for (int p = 0; p < 4; p++) {
                int nrow = wj * 64 + p * 16 + b_row;
                int ch = ks * 2 + b_chsel;
                uint32_t addr = sBu + (uint32_t)(nrow * 128 + ((ch ^ (nrow & 7)) << 4));
                uint32_t bf0, bf1, bf2, bf3;
                ldsm4(addr, bf0, bf1, bf2, bf3);
#pragma unroll
                for (int mt = 0; mt < 2; mt++) {
                    mma16816(acc[mt][2 * p], afr[mt], bf0, bf1);
                    mma16816(acc[mt][2 * p + 1], afr[mt], bf2, bf3);
                }
            }
        }
        __syncthreads();
    }
#pragma unroll
    for (int mt = 0; mt < 2; mt++) {
        int r0 = i0 + wi * 32 + mt * 16 + (lane >> 2);
#pragma unroll
        for (int nt = 0; nt < 8; nt++) {
            int col = j0 + wj * 64 + nt * 8 + (lane & 3) * 2;
            float b0 = bias ? bias[col] : 0.f;
            float b1 = bias ? bias[col + 1] : 0.f;
            float v0 = acc[mt][nt][0] + b0, v1 = acc[mt][nt][1] + b1;
            float v2 = acc[mt][nt][2] + b0, v3 = acc[mt][nt][3] + b1;
            if (relu) {
                v0 = fmaxf(v0, 0.f); v1 = fmaxf(v1, 0.f);
                v2 = fmaxf(v2, 0.f); v3 = fmaxf(v3, 0.f);
            }
            if (r0 < M) {
                if (Cf) { Cf[(size_t)r0 * D + col] = v0; Cf[(size_t)r0 * D + col + 1] = v1; }
                if (Ch) {
                    Ch[(size_t)r0 * D + col] = __float2bfloat16(v0);
                    Ch[(size_t)r0 * D + col + 1] = __float2bfloat16(v1);
                }
            }
            int r1 = r0 + 8;
            if (r1 < M) {
                if (Cf) { Cf[(size_t)r1 * D + col] = v2; Cf[(size_t)r1 * D + col + 1] = v3; }
                if (Ch) {
                    Ch[(size_t)r1 * D + col] = __float2bfloat16(v2);
                    Ch[(size_t)r1 * D + col + 1] = __float2bfloat16(v3);
                }
            }
        }
    }
}

// ---------------- fused dual negsum (HMMA): s1 += rowsum exp(2 z.z'), s2 += rowsum exp(2 z.q') ----------------
__global__ __launch_bounds__(256, 2) void negmma2_k(
    const __nv_bfloat16* __restrict__ Z, const __nv_bfloat16* __restrict__ Q,
    float* __restrict__ s1, float* __restrict__ s2, int n, int nJT) {
    extern __shared__ char dsm[];
    uint32_t aBase = (uint32_t)__cvta_generic_to_shared(dsm);        // 65536 B
    uint32_t bBase = aBase + 65536;                                   // 2 x 16384 B
    int tid = threadIdx.x;
    int lane = tid & 31, warp = tid >> 5;
    int wi = warp >> 1, wj = warp & 1;
    int i0 = blockIdx.x * 128;

    int a_row = (lane & 15);
    int a_chsel = (lane >> 4);
    int b_row = (lane & 7) + ((lane >> 4) & 1) * 8;
    int b_chsel = ((lane >> 3) & 1);

    // resident A load: 4096 x 16B chunks, blocked [4][128 rows][8 ch]
#pragma unroll
    for (int t = 0; t < 16; t++) {
        int c = tid + t * 256;
        int blk = c >> 10, idx = c & 1023;
        int row = idx >> 3, ch = idx & 7;
        uint32_t off = (uint32_t)(blk * 16384 + row * 128 + ((ch ^ (row & 7)) << 4));
        cp16(aBase + off, Z + (size_t)(i0 + row) * D + blk * 64 + ch * 8);
    }
    asm volatile("cp.async.commit_group;" ::: "memory");

    float rs[2][2][2];  // [sel][mt][h]
#pragma unroll
    for (int a = 0; a < 2; a++)
#pragma unroll
        for (int b = 0; b < 2; b++)
#pragma unroll
            for (int c = 0; c < 2; c++) rs[a][b][c] = 0.f;

    for (int jt = blockIdx.y; jt < nJT; jt += gridDim.y) {
        int j0 = jt * 128;
#pragma unroll 1
        for (int sel = 0; sel < 2; sel++) {
            const __nv_bfloat16* Bg = (sel ? Q : Z) + (size_t)j0 * D;
            loadB64(bBase, Bg, 0, D, tid);
            float acc[2][8][4];
#pragma unroll
            for (int x = 0; x < 2; x++)
#pragma unroll
                for (int y = 0; y < 8; y++)
#pragma unroll
                    for (int v = 0; v < 4; v++) acc[x][y][v] = 0.f;

#pragma unroll
            for (int kt = 0; kt < 4; kt++) {
                asm volatile("cp.async.wait_group 0;" ::: "memory");
                __syncthreads();
                if (kt < 3) loadB64(bBase + ((kt + 1) & 1) * 16384, Bg, (kt + 1) * 64, D, tid);
                uint32_t sAu = aBase + kt * 16384;
                uint32_t sBu = bBase + (kt & 1) * 16384;
#pragma unroll
                for (int ks = 0; ks < 4; ks++) {
                    uint32_t afr[2][4];
#pragma unroll
                    for (int mt = 0; mt < 2; mt++) {
                        int row = wi * 32 + mt * 16 + a_row;
                        int ch = ks * 2 + a_chsel;
                        uint32_t addr = sAu + (uint32_t)(row * 128 + ((ch ^ (row & 7)) << 4));
                        ldsm4(addr, afr[mt][0], afr[mt][1], afr[mt][2], afr[mt][3]);
                    }
#pragma unroll
                    for (int p = 0; p < 4; p++) {
                        int nrow = wj * 64 + p * 16 + b_row;
                        int ch = ks * 2 + b_chsel;
                        uint32_t addr = sBu + (uint32_t)(nrow * 128 + ((ch ^ (nrow & 7)) << 4));
                        uint32_t bf0, bf1, bf2, bf3;
                        ldsm4(addr, bf0, bf1, bf2, bf3);
#pragma unroll
                        for (int mt = 0; mt < 2; mt++) {
                            mma16816(acc[mt][2 * p], afr[mt], bf0, bf1);
                            mma16816(acc[mt][2 * p + 1], afr[mt], bf2, bf3);
                        }
                    }
                }
                __syncthreads();
            }
            // epilogue: exp + masked rowsum
#pragma unroll
            for (int mt = 0; mt < 2; mt++) {
#pragma unroll
                for (int nt = 0; nt < 8; nt++) {
                    int j = j0 + wj * 64 + nt * 8 + (lane & 3) * 2;
                    float e0 = (j < n) ? __expf(acc[mt][nt][0] * TEMP_INV) : 0.f;
                    float e1 = (j + 1 < n) ? __expf(acc[mt][nt][1] * TEMP_INV) : 0.f;
                    float e2 = (j < n) ? __expf(acc[mt][nt][2] * TEMP_INV) : 0.f;
                    float e3 = (j + 1 < n) ? __expf(acc[mt][nt][3] * TEMP_INV) : 0.f;
                    rs[sel][mt][0] += e0 + e1;
                    rs[sel][mt][1] += e2 + e3;
                }
            }
        }
    }
#pragma unroll
    for (int sel = 0; sel < 2; sel++) {
        float* out = sel ? s2 : s1;
#pragma unroll
        for (int mt = 0; mt < 2; mt++) {
#pragma unroll
            for (int h = 0; h < 2; h++) {
                float v = rs[sel][mt][h];
                v += __shfl_xor_sync(0xffffffffu, v, 1);
                v += __shfl_xor_sync(0xffffffffu, v, 2);
                if ((lane & 3) == 0) {
                    int i = i0 + wi * 32 + mt * 16 + h * 8 + (lane >> 2);
                    if (i < n) atomicAdd(&out[i], v);
                }
            }
        }
    }
}

// ------------------------------ launcher ------------------------------
static float* symf(const void* s) { void* p = nullptr; cudaGetSymbolAddress(&p, s); return (float*)p; }
static int* symi(const void* s) { void* p = nullptr; cudaGetSymbolAddress(&p, s); return (int*)p; }
static __nv_bfloat16* symh(const void* s) { void* p = nullptr; cudaGetSymbolAddress(&p, s); return (__nv_bfloat16*)p; }

extern "C" void kernel_launch(void* const* d_in, const int* in_sizes, int n_in,
                              void* d_out, int out_size) {
    const float* feat  = (const float*)d_in[0];
    const float* W1    = (const float*)d_in[1];
    const float* b1    = (const float*)d_in[2];
    const float* W2    = (const float*)d_in[3];
    const float* b2    = (const float*)d_in[4];
    const float* Wt1   = (const float*)d_in[5];
    const float* bt1   = (const float*)d_in[6];
    const float* gamma = (const float*)d_in[7];
    const float* beta  = (const float*)d_in[8];
    const float* Wt2   = (const float*)d_in[9];
    const float* bt2   = (const float*)d_in[10];
    const float* Wp    = (const float*)d_in[11];
    const float* bp    = (const float*)d_in[12];
    const int*   src   = (const int*)d_in[13];
    const int*   dst   = (const int*)d_in[14];

    const int IN = 512;
    int n = in_sizes[0] / IN;
    int e = in_sizes[13];
    int nTI = (n + 127) / 128;
    int npad = nTI * 128;

    float* tbuf = symf(g_t);
    float* hbuf = symf(g_h);
    float* pbuf = symf(g_p);
    float* zbuf = symf(g_z);
    float* qbuf = symf(g_q);
    __nv_bfloat16* featb = symh(g_featb);
    __nv_bfloat16* xwb = symh(g_xwb);
    __nv_bfloat16* h1b = symh(g_h1b);
    __nv_bfloat16* tb = symh(g_tb);
    __nv_bfloat16* transb = symh(g_transb);
    __nv_bfloat16* zh = symh(g_zh);
    __nv_bfloat16* qh = symh(g_qh);
    __nv_bfloat16* W1b = symh(g_W1b);
    __nv_bfloat16* W2b = symh(g_W2b);
    __nv_bfloat16* Wt1b = symh(g_Wt1b);
    __nv_bfloat16* Wt2b = symh(g_Wt2b);
    __nv_bfloat16* Wpb = symh(g_Wpb);
    float* dout = symf(g_degout);
    float* din  = symf(g_degin);
    float* rsd  = symf(g_rsd);
    int* cnt = symi(g_cnt);
    int* off = symi(g_off);
    int* cur = symi(g_cur);
    int* csrc = symi(g_csrc);
    float* musum = symf(g_musum);
    float* varsum = symf(g_varsum);
    float* s1 = symf(g_s1);
    float* s2 = symf(g_s2);
    float* pos = symf(g_pos);
    float* out = (float*)d_out;

    int nd = n * D;
    int ndpad = npad * D;
    int tail = ndpad - nd;
    dim3 gemm_grid(nTI, 2);
    int node_warp_blocks = (n * 32 + 255) / 256;

    // streams/events created once (not work; same captured graph every call)
    static cudaStream_t sA = nullptr, sB = nullptr;
    static cudaEvent_t evStart, evRoot, evCSR, evGCN, evNorm, evPos;
    if (sA == nullptr) {
        cudaStreamCreateWithFlags(&sA, cudaStreamNonBlocking);
        cudaStreamCreateWithFlags(&sB, cudaStreamNonBlocking);
        cudaEventCreateWithFlags(&evStart, cudaEventDisableTiming);
        cudaEventCreateWithFlags(&evRoot, cudaEventDisableTiming);
        cudaEventCreateWithFlags(&evCSR, cudaEventDisableTiming);
        cudaEventCreateWithFlags(&evGCN, cudaEventDisableTiming);
        cudaEventCreateWithFlags(&evNorm, cudaEventDisableTiming);
        cudaEventCreateWithFlags(&evPos, cudaEventDisableTiming);
        cudaFuncSetAttribute(gemm_bf16_k, cudaFuncAttributeMaxDynamicSharedMemorySize, 2 * STAGE_BYTES);
        cudaFuncSetAttribute(negmma2_k, cudaFuncAttributeMaxDynamicSharedMemorySize, 98304);
    }

    // ---- fork CSR chain to sB (independent of conversions) ----
    cudaEventRecord(evStart, 0);
    cudaStreamWaitEvent(sB, evStart, 0);
    zero3_k<<<(n + 255) / 256, 256, 0, sB>>>(dout, din, cnt, n);
    degree_k<<<(e + 255) / 256, 256, 0, sB>>>(src, dst, dout, din, cnt, e);
    rsdcur_k<<<(n + 255) / 256, 256, 0, sB>>>(dout, rsd, cur, n);
    scan_k<<<1, 1024, 0, sB>>>(cnt, off, n);
    fillcsr_k<<<(e + 255) / 256, 256, 0, sB>>>(src, dst, off, cur, csrc, e);
    cudaEventRecord(evCSR, sB);

    // ---- main: conversions ----
    f2b_k<<<(npad * IN + 255) / 256, 256>>>(feat, featb, n * IN, npad * IN);
    wconvall_k<<<(458752 + 255) / 256, 256>>>(W1, Wt1, W2, Wt2, Wp,
                                              W1b, Wt1b, W2b, Wt2b, Wpb);
    cudaEventRecord(evRoot, 0);

    // ---- fork GCN branch to sA ----
    cudaStreamWaitEvent(sA, evRoot, 0);
    gemm_bf16_k<<<gemm_grid, 256, 2 * STAGE_BYTES, sA>>>(featb, W1b, nullptr, nullptr, xwb, n, IN, 0);
    cudaStreamWaitEvent(sA, evCSR, 0);
    gather_agg_k<<<node_warp_blocks, 256, 0, sA>>>(xwb, csrc, off, rsd, din, b1, nullptr, h1b, n, 1);
    zerohtail_k<<<(tail + 255) / 256, 256, 0, sA>>>(h1b, nd, ndpad);
    gemm_bf16_k<<<gemm_grid, 256, 2 * STAGE_BYTES, sA>>>(h1b, W2b, nullptr, nullptr, xwb, n, D, 0);
    gather_agg_k<<<node_warp_blocks, 256, 0, sA>>>(xwb, csrc, off, rsd, din, b2, hbuf, nullptr, n, 0);
    cudaEventRecord(evGCN, sA);

    // ---- main: target MLP branch ----
    gemm_bf16_k<<<gemm_grid, 256, 2 * STAGE_BYTES>>>(featb, Wt1b, bt1, tbuf, nullptr, n, IN, 0);
    zero2_k<<<1, 256>>>(musum, varsum, D);
    bnstat_k<<<100, 256>>>(tbuf, musum, varsum, n);
    bnapply_k<<<(nd + 255) / 256, 256>>>(tbuf, musum, varsum, gamma, beta, tb, n);
    zerohtail_k<<<(tail + 255) / 256, 256>>>(tb, nd, ndpad);
    gemm_bf16_k<<<gemm_grid, 256, 2 * STAGE_BYTES>>>(tb, Wt2b, bt2, nullptr, transb, n, D, 0);
    zerohtail_k<<<(tail + 255) / 256, 256>>>(transb, nd, ndpad);
    gemm_bf16_k<<<gemm_grid, 256, 2 * STAGE_BYTES>>>(transb, Wpb, bp, pbuf, nullptr, n, D, 0);
    zero2_k<<<(n + 255) / 256, 256>>>(s1, s2, n);
    zero_k<<<1, 32>>>(out, out_size);

    // ---- join: normalize both (needs hbuf from sA, pbuf from main) ----
    cudaStreamWaitEvent(0, evGCN, 0);
    dim3 norm_grid((npad * 32 + 255) / 256, 2);
    norml2_k<<<norm_grid, 256>>>(hbuf, zbuf, zh, pbuf, qbuf, qh, n, npad);
    cudaEventRecord(evNorm, 0);

    // ---- fork pos to sA, run negsum on main concurrently ----
    cudaStreamWaitEvent(sA, evNorm, 0);
    gather_pos_k<<<node_warp_blocks, 256, 0, sA>>>(zh, qh, csrc, off, pos, n);
    cudaEventRecord(evPos, sA);

    dim3 neg_grid(nTI, 24);
    negmma2_k<<<neg_grid, 256, 98304>>>(zh, qh, s1, s2, n, nTI);

    // ---- join + fused mneg + loss ----
    cudaStreamWaitEvent(0, evPos, 0);
    mneg_loss_k<<<node_warp_blocks, 256>>>(s1, s2, pos, csrc, off, out, n);
}